// round 1
// baseline (speedup 1.0000x reference)
#include <cuda_runtime.h>
#include <math.h>

#define B_   8
#define S_   2048
#define MD   1024
#define DK   128
#define NROWS (B_*S_)

// scratch for projected q,k,v  (8.39 MB each)
__device__ float g_q[NROWS*DK];
__device__ float g_k[NROWS*DK];
__device__ float g_v[NROWS*DK];

// ---------------- projection: Y[16384,128] = X[16384,1024] @ W[128,1024]^T ----
__global__ __launch_bounds__(256) void proj_kernel(
    const float* __restrict__ Xq, const float* __restrict__ Xk, const float* __restrict__ Xv,
    const float* __restrict__ Wq, const float* __restrict__ Wk, const float* __restrict__ Wv)
{
    const float* X; const float* W; float* Y;
    if (blockIdx.y == 0)      { X = Xq; W = Wq; Y = g_q; }
    else if (blockIdx.y == 1) { X = Xk; W = Wk; Y = g_k; }
    else                      { X = Xv; W = Wv; Y = g_v; }

    __shared__ float As[16][64];    // [k][m]
    __shared__ float Bs[16][128];   // [k][n]

    const int tid  = threadIdx.x;
    const int row0 = blockIdx.x * 64;
    const int tr = tid >> 4;        // 0..15 -> rows tr*4..+3
    const int tc = tid & 15;        // 0..15 -> cols tc*8..+7

    float acc[4][8];
    #pragma unroll
    for (int i = 0; i < 4; i++)
        #pragma unroll
        for (int j = 0; j < 8; j++) acc[i][j] = 0.f;

    const int a_row = tid >> 2;     // 0..63
    const int a_f4  = tid & 3;      // 0..3

    for (int k0 = 0; k0 < MD; k0 += 16) {
        // A tile: 64 rows x 16 k
        float4 av = *(const float4*)&X[(row0 + a_row) * MD + k0 + a_f4 * 4];
        As[a_f4*4+0][a_row] = av.x;
        As[a_f4*4+1][a_row] = av.y;
        As[a_f4*4+2][a_row] = av.z;
        As[a_f4*4+3][a_row] = av.w;
        // B tile: 16 k x 128 n  (W is [n][k] row-major)
        #pragma unroll
        for (int l = 0; l < 2; l++) {
            int i  = tid + l * 256;    // 0..511
            int n  = i >> 2;           // 0..127
            int kf = i & 3;
            float4 bv = *(const float4*)&W[n * MD + k0 + kf * 4];
            Bs[kf*4+0][n] = bv.x;
            Bs[kf*4+1][n] = bv.y;
            Bs[kf*4+2][n] = bv.z;
            Bs[kf*4+3][n] = bv.w;
        }
        __syncthreads();
        #pragma unroll
        for (int kk = 0; kk < 16; kk++) {
            float4 a4 = *(const float4*)&As[kk][tr * 4];
            float  a[4] = {a4.x, a4.y, a4.z, a4.w};
            float4 b0 = *(const float4*)&Bs[kk][tc * 8];
            float4 b1 = *(const float4*)&Bs[kk][tc * 8 + 4];
            float  b[8] = {b0.x, b0.y, b0.z, b0.w, b1.x, b1.y, b1.z, b1.w};
            #pragma unroll
            for (int i = 0; i < 4; i++)
                #pragma unroll
                for (int j = 0; j < 8; j++)
                    acc[i][j] += a[i] * b[j];
        }
        __syncthreads();
    }
    #pragma unroll
    for (int i = 0; i < 4; i++) {
        int r = row0 + tr * 4 + i;
        float4 o0 = {acc[i][0], acc[i][1], acc[i][2], acc[i][3]};
        float4 o1 = {acc[i][4], acc[i][5], acc[i][6], acc[i][7]};
        *(float4*)&Y[r * DK + tc * 8]     = o0;
        *(float4*)&Y[r * DK + tc * 8 + 4] = o1;
    }
}

// ---------------- fused flash attention, BQ=64, BK=64, fp32 ------------------
__global__ __launch_bounds__(256) void attn_kernel(const int* __restrict__ mask,
                                                   float* __restrict__ out)
{
    extern __shared__ float sm[];
    float* Qs   = sm;                 // 64*128
    float* KVs  = Qs  + 64 * 128;     // 64*128 (K, then reused for V)
    float* Ss   = KVs + 64 * 128;     // 64*65  (scores / probabilities)
    float* m_sm = Ss  + 64 * 65;      // 64
    float* l_sm = m_sm + 64;          // 64
    float* c_sm = l_sm + 64;          // 64

    const int tid = threadIdx.x;
    const int qt  = blockIdx.x;       // 0..31
    const int b   = blockIdx.y;       // 0..7

    const float* Qg = g_q + ((long long)b * S_ + qt * 64) * DK;
    const float* Kg = g_k + (long long)b * S_ * DK;
    const float* Vg = g_v + (long long)b * S_ * DK;

    #pragma unroll
    for (int i = 0; i < 8; i++) {
        int idx = tid + i * 256;      // 2048 float4 = 64x128
        ((float4*)Qs)[idx] = ((const float4*)Qg)[idx];
    }
    if (tid < 64) { m_sm[tid] = -1e30f; l_sm[tid] = 0.f; }

    const int tr = tid >> 4, tc = tid & 15;
    const int wid = tid >> 5, lane = tid & 31;

    float acc[4][8];
    #pragma unroll
    for (int i = 0; i < 4; i++)
        #pragma unroll
        for (int j = 0; j < 8; j++) acc[i][j] = 0.f;

    const float scale = 0.08838834764831845f;   // 1/sqrt(128)

    for (int kt = 0; kt < 32; kt++) {
        __syncthreads();   // protects KVs/Ss from previous iteration's readers
        const float* Ksrc = Kg + kt * 64 * DK;
        #pragma unroll
        for (int i = 0; i < 8; i++) {
            int idx = tid + i * 256;
            ((float4*)KVs)[idx] = ((const float4*)Ksrc)[idx];
        }
        __syncthreads();

        // S fragment: rows tr*4..+3, cols tc*4..+3
        float s[4][4];
        #pragma unroll
        for (int i = 0; i < 4; i++)
            #pragma unroll
            for (int j = 0; j < 4; j++) s[i][j] = 0.f;

        for (int d = 0; d < 128; d += 4) {
            float4 q[4], k[4];
            #pragma unroll
            for (int i = 0; i < 4; i++) q[i] = *(float4*)&Qs[(tr*4+i)*128 + d];
            #pragma unroll
            for (int j = 0; j < 4; j++) k[j] = *(float4*)&KVs[(tc*4+j)*128 + d];
            #pragma unroll
            for (int i = 0; i < 4; i++)
                #pragma unroll
                for (int j = 0; j < 4; j++)
                    s[i][j] += q[i].x*k[j].x + q[i].y*k[j].y
                             + q[i].z*k[j].z + q[i].w*k[j].w;
        }

        // mask + scale -> Ss
        #pragma unroll
        for (int i = 0; i < 4; i++) {
            int qrow = qt * 64 + tr * 4 + i;
            const int* mrow = mask + ((long long)b * S_ + qrow) * S_ + kt * 64 + tc * 4;
            int4 mv = *(const int4*)mrow;
            float* srow = &Ss[(tr*4+i)*65 + tc*4];
            srow[0] = mv.x ? s[i][0] * scale : -1e9f;
            srow[1] = mv.y ? s[i][1] * scale : -1e9f;
            srow[2] = mv.z ? s[i][2] * scale : -1e9f;
            srow[3] = mv.w ? s[i][3] * scale : -1e9f;
        }
        __syncthreads();

        // load V over K (all K reads finished at the sync above)
        const float* Vsrc = Vg + kt * 64 * DK;
        #pragma unroll
        for (int i = 0; i < 8; i++) {
            int idx = tid + i * 256;
            ((float4*)KVs)[idx] = ((const float4*)Vsrc)[idx];
        }

        // online softmax: warp wid owns rows wid*8..+7; lane owns 2 cols
        #pragma unroll
        for (int rr = 0; rr < 8; rr++) {
            int r = wid * 8 + rr;
            float v0 = Ss[r*65 + lane*2];
            float v1 = Ss[r*65 + lane*2 + 1];
            float mx = fmaxf(v0, v1);
            #pragma unroll
            for (int off = 16; off > 0; off >>= 1)
                mx = fmaxf(mx, __shfl_xor_sync(0xffffffffu, mx, off));
            float m_old = m_sm[r];
            float m_new = fmaxf(m_old, mx);
            float p0 = __expf(v0 - m_new);
            float p1 = __expf(v1 - m_new);
            float sum = p0 + p1;
            #pragma unroll
            for (int off = 16; off > 0; off >>= 1)
                sum += __shfl_xor_sync(0xffffffffu, sum, off);
            Ss[r*65 + lane*2]     = p0;
            Ss[r*65 + lane*2 + 1] = p1;
            if (lane == 0) {
                float corr = __expf(m_old - m_new);
                l_sm[r] = l_sm[r] * corr + sum;
                m_sm[r] = m_new;
                c_sm[r] = corr;
            }
        }
        __syncthreads();

        // rescale accumulators, then acc += P @ V
        float corr[4];
        #pragma unroll
        for (int i = 0; i < 4; i++) corr[i] = c_sm[tr*4 + i];
        #pragma unroll
        for (int i = 0; i < 4; i++)
            #pragma unroll
            for (int j = 0; j < 8; j++) acc[i][j] *= corr[i];

        for (int k = 0; k < 64; k++) {
            float p[4];
            #pragma unroll
            for (int i = 0; i < 4; i++) p[i] = Ss[(tr*4+i)*65 + k];
            float4 v0 = *(float4*)&KVs[k*128 + tc*8];
            float4 v1 = *(float4*)&KVs[k*128 + tc*8 + 4];
            float  v[8] = {v0.x, v0.y, v0.z, v0.w, v1.x, v1.y, v1.z, v1.w};
            #pragma unroll
            for (int i = 0; i < 4; i++)
                #pragma unroll
                for (int j = 0; j < 8; j++)
                    acc[i][j] += p[i] * v[j];
        }
    }
    __syncthreads();

    #pragma unroll
    for (int i = 0; i < 4; i++) {
        int r = tr * 4 + i;
        float inv_l = 1.f / l_sm[r];
        long long ro = ((long long)b * S_ + qt * 64 + r) * DK;
        float4 o0 = {acc[i][0]*inv_l, acc[i][1]*inv_l, acc[i][2]*inv_l, acc[i][3]*inv_l};
        float4 o1 = {acc[i][4]*inv_l, acc[i][5]*inv_l, acc[i][6]*inv_l, acc[i][7]*inv_l};
        *(float4*)&out[ro + tc*8]     = o0;
        *(float4*)&out[ro + tc*8 + 4] = o1;
    }
}

#define ATTN_SMEM_BYTES ((64*128 + 64*128 + 64*65 + 3*64) * sizeof(float))

extern "C" void kernel_launch(void* const* d_in, const int* in_sizes, int n_in,
                              void* d_out, int out_size)
{
    const float* query = (const float*)d_in[0];
    const float* key   = (const float*)d_in[1];
    const float* value = (const float*)d_in[2];
    const int*   maskp = (const int*)  d_in[3];
    const float* Wq    = (const float*)d_in[4];
    const float* Wk    = (const float*)d_in[5];
    const float* Wv    = (const float*)d_in[6];
    float* out = (float*)d_out;

    cudaFuncSetAttribute(attn_kernel, cudaFuncAttributeMaxDynamicSharedMemorySize,
                         (int)ATTN_SMEM_BYTES);

    proj_kernel<<<dim3(NROWS/64, 3), 256>>>(query, key, value, Wq, Wk, Wv);
    attn_kernel<<<dim3(S_/64, B_), 256, ATTN_SMEM_BYTES>>>(maskp, out);
}

// round 3
// speedup vs baseline: 2.5427x; 2.5427x over previous
#include <cuda_runtime.h>
#include <cstdint>
#include <math.h>

#define B_   8
#define S_   2048
#define MD   1024
#define DK   128
#define NROWS (B_*S_)

// projected q,k,v scratch (8.39 MB each)
__device__ float g_q[NROWS*DK];
__device__ float g_k[NROWS*DK];
__device__ float g_v[NROWS*DK];

// ===================== mma.sync tf32 helper (generic PTX, sm_80+) =====================
__device__ __forceinline__ void mma_tf32(float c[4],
                                         uint32_t a0, uint32_t a1, uint32_t a2, uint32_t a3,
                                         uint32_t b0, uint32_t b1)
{
    asm volatile("mma.sync.aligned.m16n8k8.row.col.f32.tf32.tf32.f32 "
                 "{%0,%1,%2,%3}, {%4,%5,%6,%7}, {%8,%9}, {%0,%1,%2,%3};"
                 : "+f"(c[0]), "+f"(c[1]), "+f"(c[2]), "+f"(c[3])
                 : "r"(a0), "r"(a1), "r"(a2), "r"(a3), "r"(b0), "r"(b1));
}

__device__ __forceinline__ float tf32_hi(float x) {
    return __uint_as_float(__float_as_uint(x) & 0xffffe000u);
}

// ===================== projection: tensor-core tf32 3x-split =====================
// Y[16384,128] = X[16384,1024] @ W[128,1024]^T
// CTA: 128 rows x 128 cols, 256 threads (8 warps, 4x2), warp tile 32x64.
// K staged in chunks of 32 with pad-36 smem rows (conflict-free fragment LDS).

#define PSTR 36                                   // padded row stride (floats)
#define P_SMEM_FLOATS (4 * 128 * PSTR)            // Ah, Al, Bh, Bl
#define P_SMEM_BYTES  (P_SMEM_FLOATS * 4)         // 73728 B

__global__ __launch_bounds__(256) void proj_mma(
    const float* __restrict__ Xq, const float* __restrict__ Xk, const float* __restrict__ Xv,
    const float* __restrict__ Wq, const float* __restrict__ Wk, const float* __restrict__ Wv)
{
    const float* X; const float* W; float* Y;
    if (blockIdx.y == 0)      { X = Xq; W = Wq; Y = g_q; }
    else if (blockIdx.y == 1) { X = Xk; W = Wk; Y = g_k; }
    else                      { X = Xv; W = Wv; Y = g_v; }

    extern __shared__ float smp[];
    float* Ah = smp;
    float* Al = Ah + 128 * PSTR;
    float* Bh = Al + 128 * PSTR;
    float* Bl = Bh + 128 * PSTR;

    const int tid  = threadIdx.x;
    const int wid  = tid >> 5, lane = tid & 31;
    const int wr   = wid >> 1, wc = wid & 1;       // 4x2 warp grid
    const int rowt = lane >> 2;                    // 0..7
    const int colt = lane & 3;                     // 0..3
    const int row0 = blockIdx.x * 128;

    float acc[2][8][4];
    #pragma unroll
    for (int mt = 0; mt < 2; mt++)
        #pragma unroll
        for (int nt = 0; nt < 8; nt++)
            #pragma unroll
            for (int i = 0; i < 4; i++) acc[mt][nt][i] = 0.f;

    #pragma unroll 1
    for (int k0 = 0; k0 < MD; k0 += 32) {
        // ---- stage A (128x32) and B (128x32), split hi/lo ----
        #pragma unroll
        for (int t = 0; t < 4; t++) {
            int idx = tid + t * 256;               // 0..1023 float4
            int row = idx >> 3, f4 = idx & 7;
            float4 a = *(const float4*)(X + (size_t)(row0 + row) * MD + k0 + f4 * 4);
            float4 ah = { tf32_hi(a.x), tf32_hi(a.y), tf32_hi(a.z), tf32_hi(a.w) };
            float4 al = { a.x - ah.x, a.y - ah.y, a.z - ah.z, a.w - ah.w };
            *(float4*)&Ah[row * PSTR + f4 * 4] = ah;
            *(float4*)&Al[row * PSTR + f4 * 4] = al;

            float4 b = *(const float4*)(W + (size_t)row * MD + k0 + f4 * 4);
            float4 bh = { tf32_hi(b.x), tf32_hi(b.y), tf32_hi(b.z), tf32_hi(b.w) };
            float4 bl = { b.x - bh.x, b.y - bh.y, b.z - bh.z, b.w - bh.w };
            *(float4*)&Bh[row * PSTR + f4 * 4] = bh;
            *(float4*)&Bl[row * PSTR + f4 * 4] = bl;
        }
        __syncthreads();

        // ---- 4 k8 chunks of mma ----
        #pragma unroll
        for (int k8 = 0; k8 < 4; k8++) {
            const int kb = k8 * 8;
            uint32_t ahf[2][4], alf[2][4];
            #pragma unroll
            for (int mt = 0; mt < 2; mt++) {
                int r = wr * 32 + mt * 16;
                int o0 = (r + rowt) * PSTR + kb + colt;
                int o1 = (r + rowt + 8) * PSTR + kb + colt;
                ahf[mt][0] = __float_as_uint(Ah[o0]);
                ahf[mt][1] = __float_as_uint(Ah[o1]);
                ahf[mt][2] = __float_as_uint(Ah[o0 + 4]);
                ahf[mt][3] = __float_as_uint(Ah[o1 + 4]);
                alf[mt][0] = __float_as_uint(Al[o0]);
                alf[mt][1] = __float_as_uint(Al[o1]);
                alf[mt][2] = __float_as_uint(Al[o0 + 4]);
                alf[mt][3] = __float_as_uint(Al[o1 + 4]);
            }
            #pragma unroll
            for (int nt = 0; nt < 8; nt++) {
                int n = wc * 64 + nt * 8 + rowt;
                int ob = n * PSTR + kb + colt;
                uint32_t bh0 = __float_as_uint(Bh[ob]);
                uint32_t bh1 = __float_as_uint(Bh[ob + 4]);
                uint32_t bl0 = __float_as_uint(Bl[ob]);
                uint32_t bl1 = __float_as_uint(Bl[ob + 4]);
                #pragma unroll
                for (int mt = 0; mt < 2; mt++) {
                    mma_tf32(acc[mt][nt], ahf[mt][0], ahf[mt][1], ahf[mt][2], ahf[mt][3], bh0, bh1);
                    mma_tf32(acc[mt][nt], ahf[mt][0], ahf[mt][1], ahf[mt][2], ahf[mt][3], bl0, bl1);
                    mma_tf32(acc[mt][nt], alf[mt][0], alf[mt][1], alf[mt][2], alf[mt][3], bh0, bh1);
                }
            }
        }
        __syncthreads();
    }

    // ---- epilogue ----
    #pragma unroll
    for (int mt = 0; mt < 2; mt++) {
        int gr = row0 + wr * 32 + mt * 16 + rowt;
        #pragma unroll
        for (int nt = 0; nt < 8; nt++) {
            int gc = wc * 64 + nt * 8 + colt * 2;
            float2 c01 = { acc[mt][nt][0], acc[mt][nt][1] };
            float2 c23 = { acc[mt][nt][2], acc[mt][nt][3] };
            *(float2*)(Y + (size_t)gr * DK + gc)       = c01;
            *(float2*)(Y + (size_t)(gr + 8) * DK + gc) = c23;
        }
    }
}

// ===================== fused flash attention (FFMA, 8x8 frags, swizzled) ==========
#define BQ 128
#define BK 128
#define ATTN_SMEM_FLOATS (3*128*32*4 + 3*128)
#define ATTN_SMEM_BYTES  (ATTN_SMEM_FLOATS * 4)

__global__ __launch_bounds__(256) void attn_kernel(const int* __restrict__ mask,
                                                   float* __restrict__ out)
{
    extern __shared__ float sm[];
    float4* Qs  = (float4*)sm;               // 128 rows x 32 f4, xor-swizzled
    float4* KVs = (float4*)(sm + 16384);
    float4* Ss  = (float4*)(sm + 32768);
    float* m_sm = sm + 49152;
    float* l_sm = m_sm + 128;
    float* c_sm = l_sm + 128;

    const int tid = threadIdx.x;
    const int qt = blockIdx.x, b = blockIdx.y;
    const int wid = tid >> 5, lane = tid & 31;
    const int wr = wid >> 1, wc = wid & 1;
    const int tr = wr * 4 + (lane >> 3);     // 0..15 row group (8 rows each)
    const int tc = wc * 8 + (lane & 7);      // 0..15 col group (8 cols each)

    const float4* Qg = (const float4*)(g_q + ((size_t)b * S_ + (size_t)qt * BQ) * DK);
    const float*  Kg = g_k + (size_t)b * S_ * DK;
    const float*  Vg = g_v + (size_t)b * S_ * DK;

    #pragma unroll
    for (int t = 0; t < 16; t++) {
        int idx = tid + t * 256;             // 0..4095 f4
        int row = idx >> 5, f4 = idx & 31;
        Qs[row * 32 + (f4 ^ ((row >> 3) & 7))] = Qg[idx];
    }
    if (tid < 128) { m_sm[tid] = -1e30f; l_sm[tid] = 0.f; }

    float acc[8][8];
    #pragma unroll
    for (int i = 0; i < 8; i++)
        #pragma unroll
        for (int j = 0; j < 8; j++) acc[i][j] = 0.f;

    const float scale = 0.08838834764831845f;     // 1/sqrt(128)

    #pragma unroll 1
    for (int kt = 0; kt < S_ / BK; kt++) {
        __syncthreads();
        const float4* Ksrc = (const float4*)(Kg + (size_t)kt * BK * DK);
        #pragma unroll
        for (int t = 0; t < 16; t++) {
            int idx = tid + t * 256;
            int row = idx >> 5, f4 = idx & 31;
            KVs[row * 32 + (f4 ^ ((row >> 3) & 7))] = Ksrc[idx];
        }
        __syncthreads();

        // ---- QK^T ----
        float s[8][8];
        #pragma unroll
        for (int i = 0; i < 8; i++)
            #pragma unroll
            for (int j = 0; j < 8; j++) s[i][j] = 0.f;

        #pragma unroll 1
        for (int d = 0; d < 128; d += 4) {
            int c = d >> 2;
            float4 q[8];
            #pragma unroll
            for (int i = 0; i < 8; i++)
                q[i] = Qs[(tr * 8 + i) * 32 + (c ^ (tr & 7))];
            #pragma unroll
            for (int j = 0; j < 8; j++) {
                float4 k4 = KVs[(tc * 8 + j) * 32 + (c ^ (tc & 7))];
                #pragma unroll
                for (int i = 0; i < 8; i++)
                    s[i][j] += q[i].x * k4.x + q[i].y * k4.y
                             + q[i].z * k4.z + q[i].w * k4.w;
            }
        }

        // ---- mask + scale -> Ss ----
        const int* mbase = mask + ((size_t)b * S_ + (size_t)qt * BQ) * S_ + (size_t)kt * BK;
        #pragma unroll
        for (int i = 0; i < 8; i++) {
            int r = tr * 8 + i;
            const int* mrow = mbase + (size_t)r * S_ + tc * 8;
            int4 m0 = *(const int4*)mrow;
            int4 m1 = *(const int4*)(mrow + 4);
            float4 p0, p1;
            p0.x = m0.x ? s[i][0] * scale : -1e9f;
            p0.y = m0.y ? s[i][1] * scale : -1e9f;
            p0.z = m0.z ? s[i][2] * scale : -1e9f;
            p0.w = m0.w ? s[i][3] * scale : -1e9f;
            p1.x = m1.x ? s[i][4] * scale : -1e9f;
            p1.y = m1.y ? s[i][5] * scale : -1e9f;
            p1.z = m1.z ? s[i][6] * scale : -1e9f;
            p1.w = m1.w ? s[i][7] * scale : -1e9f;
            Ss[r * 32 + ((tc * 2)     ^ (tr & 7))] = p0;
            Ss[r * 32 + ((tc * 2 + 1) ^ (tr & 7))] = p1;
        }
        __syncthreads();

        // ---- load V over K ----
        const float4* Vsrc = (const float4*)(Vg + (size_t)kt * BK * DK);
        #pragma unroll
        for (int t = 0; t < 16; t++) {
            int idx = tid + t * 256;
            int row = idx >> 5, f4 = idx & 31;
            KVs[row * 32 + (f4 ^ ((row >> 3) & 7))] = Vsrc[idx];
        }

        // ---- online softmax ----
        #pragma unroll 1
        for (int rr = 0; rr < 16; rr++) {
            int r = wid * 16 + rr;
            int a = r * 32 + (lane ^ ((r >> 3) & 7));
            float4 sv = Ss[a];
            float mx = fmaxf(fmaxf(sv.x, sv.y), fmaxf(sv.z, sv.w));
            #pragma unroll
            for (int off = 16; off > 0; off >>= 1)
                mx = fmaxf(mx, __shfl_xor_sync(0xffffffffu, mx, off));
            float m_old = m_sm[r];
            float m_new = fmaxf(m_old, mx);
            float4 p;
            p.x = __expf(sv.x - m_new);
            p.y = __expf(sv.y - m_new);
            p.z = __expf(sv.z - m_new);
            p.w = __expf(sv.w - m_new);
            float sum = p.x + p.y + p.z + p.w;
            #pragma unroll
            for (int off = 16; off > 0; off >>= 1)
                sum += __shfl_xor_sync(0xffffffffu, sum, off);
            Ss[a] = p;
            if (lane == 0) {
                float corr = __expf(m_old - m_new);
                l_sm[r] = l_sm[r] * corr + sum;
                m_sm[r] = m_new;
                c_sm[r] = corr;
            }
        }
        __syncthreads();

        // ---- rescale + acc += P @ V ----
        float corr[8];
        #pragma unroll
        for (int i = 0; i < 8; i++) corr[i] = c_sm[tr * 8 + i];
        #pragma unroll
        for (int i = 0; i < 8; i++)
            #pragma unroll
            for (int j = 0; j < 8; j++) acc[i][j] *= corr[i];

        #pragma unroll 1
        for (int kk = 0; kk < 128; kk += 4) {
            int c = kk >> 2;
            float4 p[8];
            #pragma unroll
            for (int i = 0; i < 8; i++)
                p[i] = Ss[(tr * 8 + i) * 32 + (c ^ (tr & 7))];
            #pragma unroll
            for (int t = 0; t < 4; t++) {
                int vr = kk + t;
                int swz = (vr >> 3) & 7;
                float4 v0 = KVs[vr * 32 + ((tc * 2)     ^ swz)];
                float4 v1 = KVs[vr * 32 + ((tc * 2 + 1) ^ swz)];
                #pragma unroll
                for (int i = 0; i < 8; i++) {
                    float pv = (t == 0) ? p[i].x : (t == 1) ? p[i].y : (t == 2) ? p[i].z : p[i].w;
                    acc[i][0] += pv * v0.x;  acc[i][1] += pv * v0.y;
                    acc[i][2] += pv * v0.z;  acc[i][3] += pv * v0.w;
                    acc[i][4] += pv * v1.x;  acc[i][5] += pv * v1.y;
                    acc[i][6] += pv * v1.z;  acc[i][7] += pv * v1.w;
                }
            }
        }
    }
    __syncthreads();

    #pragma unroll
    for (int i = 0; i < 8; i++) {
        int r = tr * 8 + i;
        float inv_l = 1.f / l_sm[r];
        float* orow = out + ((size_t)b * S_ + (size_t)qt * BQ + r) * DK + tc * 8;
        float4 o0 = { acc[i][0]*inv_l, acc[i][1]*inv_l, acc[i][2]*inv_l, acc[i][3]*inv_l };
        float4 o1 = { acc[i][4]*inv_l, acc[i][5]*inv_l, acc[i][6]*inv_l, acc[i][7]*inv_l };
        *(float4*)orow       = o0;
        *(float4*)(orow + 4) = o1;
    }
}

// ===================== launch =====================
extern "C" void kernel_launch(void* const* d_in, const int* in_sizes, int n_in,
                              void* d_out, int out_size)
{
    const float* query = (const float*)d_in[0];
    const float* key   = (const float*)d_in[1];
    const float* value = (const float*)d_in[2];
    const int*   maskp = (const int*)  d_in[3];
    const float* Wq    = (const float*)d_in[4];
    const float* Wk    = (const float*)d_in[5];
    const float* Wv    = (const float*)d_in[6];
    float* out = (float*)d_out;

    cudaFuncSetAttribute(proj_mma, cudaFuncAttributeMaxDynamicSharedMemorySize,
                         (int)P_SMEM_BYTES);
    cudaFuncSetAttribute(attn_kernel, cudaFuncAttributeMaxDynamicSharedMemorySize,
                         (int)ATTN_SMEM_BYTES);

    proj_mma<<<dim3(NROWS / 128, 3), 256, P_SMEM_BYTES>>>(query, key, value, Wq, Wk, Wv);
    attn_kernel<<<dim3(S_ / BQ, B_), 256, ATTN_SMEM_BYTES>>>(maskp, out);
}

// round 5
// speedup vs baseline: 2.8311x; 1.1134x over previous
#include <cuda_runtime.h>
#include <cstdint>
#include <math.h>

#define B_   8
#define S_   2048
#define MD   1024
#define DK   128
#define NROWS (B_*S_)

// projected q,k,v scratch (8.39 MB each)
__device__ float g_q[NROWS*DK];
__device__ float g_k[NROWS*DK];
__device__ float g_v[NROWS*DK];

// ===================== mma.sync tf32 helper (generic PTX, sm_80+) =====================
__device__ __forceinline__ void mma_tf32(float c[4],
                                         uint32_t a0, uint32_t a1, uint32_t a2, uint32_t a3,
                                         uint32_t b0, uint32_t b1)
{
    asm volatile("mma.sync.aligned.m16n8k8.row.col.f32.tf32.tf32.f32 "
                 "{%0,%1,%2,%3}, {%4,%5,%6,%7}, {%8,%9}, {%0,%1,%2,%3};"
                 : "+f"(c[0]), "+f"(c[1]), "+f"(c[2]), "+f"(c[3])
                 : "r"(a0), "r"(a1), "r"(a2), "r"(a3), "r"(b0), "r"(b1));
}

__device__ __forceinline__ float tf32_hi(float x) {
    return __uint_as_float(__float_as_uint(x) & 0xffffe000u);
}

// ===================== projection: tensor-core tf32 3x-split (validated) ==========
#define PSTR 36
#define P_SMEM_FLOATS (4 * 128 * PSTR)
#define P_SMEM_BYTES  (P_SMEM_FLOATS * 4)

__global__ __launch_bounds__(256) void proj_mma(
    const float* __restrict__ Xq, const float* __restrict__ Xk, const float* __restrict__ Xv,
    const float* __restrict__ Wq, const float* __restrict__ Wk, const float* __restrict__ Wv)
{
    const float* X; const float* W; float* Y;
    if (blockIdx.y == 0)      { X = Xq; W = Wq; Y = g_q; }
    else if (blockIdx.y == 1) { X = Xk; W = Wk; Y = g_k; }
    else                      { X = Xv; W = Wv; Y = g_v; }

    extern __shared__ float smp[];
    float* Ah = smp;
    float* Al = Ah + 128 * PSTR;
    float* Bh = Al + 128 * PSTR;
    float* Bl = Bh + 128 * PSTR;

    const int tid  = threadIdx.x;
    const int wid  = tid >> 5, lane = tid & 31;
    const int wr   = wid >> 1, wc = wid & 1;
    const int rowt = lane >> 2;
    const int colt = lane & 3;
    const int row0 = blockIdx.x * 128;

    float acc[2][8][4];
    #pragma unroll
    for (int mt = 0; mt < 2; mt++)
        #pragma unroll
        for (int nt = 0; nt < 8; nt++)
            #pragma unroll
            for (int i = 0; i < 4; i++) acc[mt][nt][i] = 0.f;

    #pragma unroll 1
    for (int k0 = 0; k0 < MD; k0 += 32) {
        #pragma unroll
        for (int t = 0; t < 4; t++) {
            int idx = tid + t * 256;
            int row = idx >> 3, f4 = idx & 7;
            float4 a = *(const float4*)(X + (size_t)(row0 + row) * MD + k0 + f4 * 4);
            float4 ah = { tf32_hi(a.x), tf32_hi(a.y), tf32_hi(a.z), tf32_hi(a.w) };
            float4 al = { a.x - ah.x, a.y - ah.y, a.z - ah.z, a.w - ah.w };
            *(float4*)&Ah[row * PSTR + f4 * 4] = ah;
            *(float4*)&Al[row * PSTR + f4 * 4] = al;

            float4 b = *(const float4*)(W + (size_t)row * MD + k0 + f4 * 4);
            float4 bh = { tf32_hi(b.x), tf32_hi(b.y), tf32_hi(b.z), tf32_hi(b.w) };
            float4 bl = { b.x - bh.x, b.y - bh.y, b.z - bh.z, b.w - bh.w };
            *(float4*)&Bh[row * PSTR + f4 * 4] = bh;
            *(float4*)&Bl[row * PSTR + f4 * 4] = bl;
        }
        __syncthreads();

        #pragma unroll
        for (int k8 = 0; k8 < 4; k8++) {
            const int kb = k8 * 8;
            uint32_t ahf[2][4], alf[2][4];
            #pragma unroll
            for (int mt = 0; mt < 2; mt++) {
                int r = wr * 32 + mt * 16;
                int o0 = (r + rowt) * PSTR + kb + colt;
                int o1 = (r + rowt + 8) * PSTR + kb + colt;
                ahf[mt][0] = __float_as_uint(Ah[o0]);
                ahf[mt][1] = __float_as_uint(Ah[o1]);
                ahf[mt][2] = __float_as_uint(Ah[o0 + 4]);
                ahf[mt][3] = __float_as_uint(Ah[o1 + 4]);
                alf[mt][0] = __float_as_uint(Al[o0]);
                alf[mt][1] = __float_as_uint(Al[o1]);
                alf[mt][2] = __float_as_uint(Al[o0 + 4]);
                alf[mt][3] = __float_as_uint(Al[o1 + 4]);
            }
            #pragma unroll
            for (int nt = 0; nt < 8; nt++) {
                int n = wc * 64 + nt * 8 + rowt;
                int ob = n * PSTR + kb + colt;
                uint32_t bh0 = __float_as_uint(Bh[ob]);
                uint32_t bh1 = __float_as_uint(Bh[ob + 4]);
                uint32_t bl0 = __float_as_uint(Bl[ob]);
                uint32_t bl1 = __float_as_uint(Bl[ob + 4]);
                #pragma unroll
                for (int mt = 0; mt < 2; mt++) {
                    mma_tf32(acc[mt][nt], ahf[mt][0], ahf[mt][1], ahf[mt][2], ahf[mt][3], bh0, bh1);
                    mma_tf32(acc[mt][nt], ahf[mt][0], ahf[mt][1], ahf[mt][2], ahf[mt][3], bl0, bl1);
                    mma_tf32(acc[mt][nt], alf[mt][0], alf[mt][1], alf[mt][2], alf[mt][3], bh0, bh1);
                }
            }
        }
        __syncthreads();
    }

    #pragma unroll
    for (int mt = 0; mt < 2; mt++) {
        int gr = row0 + wr * 32 + mt * 16 + rowt;
        #pragma unroll
        for (int nt = 0; nt < 8; nt++) {
            int gc = wc * 64 + nt * 8 + colt * 2;
            float2 c01 = { acc[mt][nt][0], acc[mt][nt][1] };
            float2 c23 = { acc[mt][nt][2], acc[mt][nt][3] };
            *(float2*)(Y + (size_t)gr * DK + gc)       = c01;
            *(float2*)(Y + (size_t)(gr + 8) * DK + gc) = c23;
        }
    }
}

// ===================== tensor-core flash attention (raw smem, reg split) ==========
// BQ=BK=128, 256 threads (8 warps 4x2), warp tile 32x64.
// Raw fp32 tiles in smem; tf32 hi/lo split done in registers at frag-load time.
// Strides: Q/P = 132 (A/B-frag banks 4*rowt+colt, conflict-free),
//          KV  = 136 for V-phase (B-frag banks 8*colt+rowt, conflict-free);
//          K-phase also uses 132-style access via its own stride (132) -> use 136
//          for the shared buffer only where V lives; K gets its own stride 132? No:
//          single shared buffer, K stored stride 132, V stored stride 136.

#define SQ 132      // Q & P row stride (floats)
#define SK 132      // K row stride
#define SV 136      // V row stride
#define O_Q  0
#define O_KV (O_Q + 128*SQ)                 // max(128*SK,128*SV) = 128*136
#define O_P  (O_KV + 128*SV)
#define O_M  (O_P + 128*SQ)
#define O_L  (O_M + 128)
#define O_C  (O_L + 128)
#define A_SMEM_FLOATS (O_C + 128)
#define A_SMEM_BYTES  (A_SMEM_FLOATS * 4)   // 206,336 B

__global__ __launch_bounds__(256) void attn_tc(const int* __restrict__ mask,
                                               float* __restrict__ out)
{
    extern __shared__ float sm[];
    float* Qs  = sm + O_Q;
    float* KVs = sm + O_KV;
    float* Ps  = sm + O_P;
    float* m_sm = sm + O_M; float* l_sm = sm + O_L; float* c_sm = sm + O_C;

    const int tid = threadIdx.x;
    const int wid = tid >> 5, lane = tid & 31;
    const int wr = wid >> 1, wc = wid & 1;
    const int rowt = lane >> 2, colt = lane & 3;
    const int qt = blockIdx.x, b = blockIdx.y;

    const float4* Qg = (const float4*)(g_q + ((size_t)b * S_ + (size_t)qt * 128) * DK);
    const float*  Kg = g_k + (size_t)b * S_ * DK;
    const float*  Vg = g_v + (size_t)b * S_ * DK;

    // ---- stage Q raw ----
    #pragma unroll
    for (int t = 0; t < 16; t++) {
        int idx = tid + t * 256;             // 0..4095 float4
        int row = idx >> 5, f4 = idx & 31;
        *(float4*)&Qs[row * SQ + f4 * 4] = Qg[idx];
    }
    if (tid < 128) { m_sm[tid] = -1e30f; l_sm[tid] = 0.f; }

    float acc[2][8][4];
    #pragma unroll
    for (int mt = 0; mt < 2; mt++)
        #pragma unroll
        for (int nt = 0; nt < 8; nt++)
            #pragma unroll
            for (int i = 0; i < 4; i++) acc[mt][nt][i] = 0.f;

    const float scale = 0.08838834764831845f;   // 1/sqrt(128)

    #pragma unroll 1
    for (int kt = 0; kt < S_ / 128; kt++) {
        __syncthreads();   // prior iter done reading KVs(V) and Ps
        // ---- stage K raw (stride SK) ----
        const float4* Ksrc = (const float4*)(Kg + (size_t)kt * 128 * DK);
        #pragma unroll
        for (int t = 0; t < 16; t++) {
            int idx = tid + t * 256;
            int row = idx >> 5, f4 = idx & 31;
            *(float4*)&KVs[row * SK + f4 * 4] = Ksrc[idx];
        }
        __syncthreads();

        // ---- S = Q K^T (tf32 3-split, split in regs) ----
        float s_acc[2][8][4];
        #pragma unroll
        for (int mt = 0; mt < 2; mt++)
            #pragma unroll
            for (int nt = 0; nt < 8; nt++)
                #pragma unroll
                for (int i = 0; i < 4; i++) s_acc[mt][nt][i] = 0.f;

        #pragma unroll 1
        for (int k8 = 0; k8 < 16; k8++) {
            const int kb = k8 * 8;
            uint32_t ahf[2][4], alf[2][4];
            #pragma unroll
            for (int mt = 0; mt < 2; mt++) {
                int o0 = (wr * 32 + mt * 16 + rowt) * SQ + kb + colt;
                int o1 = o0 + 8 * SQ;
                float q0 = Qs[o0], q1 = Qs[o1], q2 = Qs[o0 + 4], q3 = Qs[o1 + 4];
                float h0 = tf32_hi(q0), h1 = tf32_hi(q1), h2 = tf32_hi(q2), h3 = tf32_hi(q3);
                ahf[mt][0] = __float_as_uint(h0);  alf[mt][0] = __float_as_uint(q0 - h0);
                ahf[mt][1] = __float_as_uint(h1);  alf[mt][1] = __float_as_uint(q1 - h1);
                ahf[mt][2] = __float_as_uint(h2);  alf[mt][2] = __float_as_uint(q2 - h2);
                ahf[mt][3] = __float_as_uint(h3);  alf[mt][3] = __float_as_uint(q3 - h3);
            }
            #pragma unroll
            for (int nt = 0; nt < 8; nt++) {
                int ob = (wc * 64 + nt * 8 + rowt) * SK + kb + colt;
                float k0 = KVs[ob], k1 = KVs[ob + 4];
                float kh0 = tf32_hi(k0), kh1 = tf32_hi(k1);
                uint32_t bh0 = __float_as_uint(kh0);
                uint32_t bh1 = __float_as_uint(kh1);
                uint32_t bl0 = __float_as_uint(k0 - kh0);
                uint32_t bl1 = __float_as_uint(k1 - kh1);
                #pragma unroll
                for (int mt = 0; mt < 2; mt++) {
                    mma_tf32(s_acc[mt][nt], ahf[mt][0], ahf[mt][1], ahf[mt][2], ahf[mt][3], bh0, bh1);
                    mma_tf32(s_acc[mt][nt], ahf[mt][0], ahf[mt][1], ahf[mt][2], ahf[mt][3], bl0, bl1);
                    mma_tf32(s_acc[mt][nt], alf[mt][0], alf[mt][1], alf[mt][2], alf[mt][3], bh0, bh1);
                }
            }
        }

        // ---- dump raw S frags into Ps ----
        #pragma unroll
        for (int mt = 0; mt < 2; mt++) {
            int r0 = wr * 32 + mt * 16 + rowt;
            #pragma unroll
            for (int nt = 0; nt < 8; nt++) {
                int c0 = wc * 64 + nt * 8 + colt * 2;
                *(float2*)&Ps[r0 * SQ + c0]       = make_float2(s_acc[mt][nt][0], s_acc[mt][nt][1]);
                *(float2*)&Ps[(r0 + 8) * SQ + c0] = make_float2(s_acc[mt][nt][2], s_acc[mt][nt][3]);
            }
        }
        __syncthreads();   // S complete; all warps done reading K

        // ---- stage V raw over K buffer (stride SV) ----
        const float4* Vsrc = (const float4*)(Vg + (size_t)kt * 128 * DK);
        #pragma unroll
        for (int t = 0; t < 16; t++) {
            int idx = tid + t * 256;
            int row = idx >> 5, f4 = idx & 31;
            *(float4*)&KVs[row * SV + f4 * 4] = Vsrc[idx];
        }

        // ---- masked online softmax (warp wid owns rows wid*16..+15) ----
        const int* mbase = mask + ((size_t)b * S_ + (size_t)qt * 128) * S_ + (size_t)kt * 128;
        #pragma unroll 1
        for (int rr = 0; rr < 16; rr++) {
            int r = wid * 16 + rr;
            float4 sv = *(float4*)&Ps[r * SQ + lane * 4];
            int4 mv = *(const int4*)(mbase + (size_t)r * S_ + lane * 4);
            float v0 = mv.x ? sv.x * scale : -1e9f;
            float v1 = mv.y ? sv.y * scale : -1e9f;
            float v2 = mv.z ? sv.z * scale : -1e9f;
            float v3 = mv.w ? sv.w * scale : -1e9f;
            float mx = fmaxf(fmaxf(v0, v1), fmaxf(v2, v3));
            #pragma unroll
            for (int off = 16; off > 0; off >>= 1)
                mx = fmaxf(mx, __shfl_xor_sync(0xffffffffu, mx, off));
            float m_old = m_sm[r];
            float m_new = fmaxf(m_old, mx);
            float p0 = __expf(v0 - m_new);
            float p1 = __expf(v1 - m_new);
            float p2 = __expf(v2 - m_new);
            float p3 = __expf(v3 - m_new);
            float sum = p0 + p1 + p2 + p3;
            #pragma unroll
            for (int off = 16; off > 0; off >>= 1)
                sum += __shfl_xor_sync(0xffffffffu, sum, off);
            *(float4*)&Ps[r * SQ + lane * 4] = make_float4(p0, p1, p2, p3);
            if (lane == 0) {
                float corr = __expf(m_old - m_new);
                l_sm[r] = l_sm[r] * corr + sum;
                m_sm[r] = m_new;
                c_sm[r] = corr;
            }
        }
        __syncthreads();

        // ---- rescale accumulators ----
        #pragma unroll
        for (int mt = 0; mt < 2; mt++) {
            int r0 = wr * 32 + mt * 16 + rowt;
            float c0 = c_sm[r0], c1 = c_sm[r0 + 8];
            #pragma unroll
            for (int nt = 0; nt < 8; nt++) {
                acc[mt][nt][0] *= c0;  acc[mt][nt][1] *= c0;
                acc[mt][nt][2] *= c1;  acc[mt][nt][3] *= c1;
            }
        }

        // ---- acc += P V (tf32 3-split, split in regs) ----
        #pragma unroll 1
        for (int k8 = 0; k8 < 16; k8++) {
            const int kb = k8 * 8;
            uint32_t ahf[2][4], alf[2][4];
            #pragma unroll
            for (int mt = 0; mt < 2; mt++) {
                int o0 = (wr * 32 + mt * 16 + rowt) * SQ + kb + colt;
                int o1 = o0 + 8 * SQ;
                float p0 = Ps[o0], p1 = Ps[o1], p2 = Ps[o0 + 4], p3 = Ps[o1 + 4];
                float h0 = tf32_hi(p0), h1 = tf32_hi(p1), h2 = tf32_hi(p2), h3 = tf32_hi(p3);
                ahf[mt][0] = __float_as_uint(h0);  alf[mt][0] = __float_as_uint(p0 - h0);
                ahf[mt][1] = __float_as_uint(h1);  alf[mt][1] = __float_as_uint(p1 - h1);
                ahf[mt][2] = __float_as_uint(h2);  alf[mt][2] = __float_as_uint(p2 - h2);
                ahf[mt][3] = __float_as_uint(h3);  alf[mt][3] = __float_as_uint(p3 - h3);
            }
            #pragma unroll
            for (int nt = 0; nt < 8; nt++) {
                int ob = (kb + colt) * SV + wc * 64 + nt * 8 + rowt;
                float v0 = KVs[ob], v1 = KVs[ob + 4 * SV];
                float vh0 = tf32_hi(v0), vh1 = tf32_hi(v1);
                uint32_t bh0 = __float_as_uint(vh0);
                uint32_t bh1 = __float_as_uint(vh1);
                uint32_t bl0 = __float_as_uint(v0 - vh0);
                uint32_t bl1 = __float_as_uint(v1 - vh1);
                #pragma unroll
                for (int mt = 0; mt < 2; mt++) {
                    mma_tf32(acc[mt][nt], ahf[mt][0], ahf[mt][1], ahf[mt][2], ahf[mt][3], bh0, bh1);
                    mma_tf32(acc[mt][nt], ahf[mt][0], ahf[mt][1], ahf[mt][2], ahf[mt][3], bl0, bl1);
                    mma_tf32(acc[mt][nt], alf[mt][0], alf[mt][1], alf[mt][2], alf[mt][3], bh0, bh1);
                }
            }
        }
    }

    // ---- epilogue: divide by l, store ----
    #pragma unroll
    for (int mt = 0; mt < 2; mt++) {
        int r0 = wr * 32 + mt * 16 + rowt;
        float il0 = 1.f / l_sm[r0];
        float il1 = 1.f / l_sm[r0 + 8];
        size_t gr = (size_t)b * S_ + (size_t)qt * 128 + r0;
        #pragma unroll
        for (int nt = 0; nt < 8; nt++) {
            int c0 = wc * 64 + nt * 8 + colt * 2;
            float2 o0 = { acc[mt][nt][0] * il0, acc[mt][nt][1] * il0 };
            float2 o1 = { acc[mt][nt][2] * il1, acc[mt][nt][3] * il1 };
            *(float2*)(out + gr * DK + c0)       = o0;
            *(float2*)(out + (gr + 8) * DK + c0) = o1;
        }
    }
}

// ===================== launch =====================
extern "C" void kernel_launch(void* const* d_in, const int* in_sizes, int n_in,
                              void* d_out, int out_size)
{
    const float* query = (const float*)d_in[0];
    const float* key   = (const float*)d_in[1];
    const float* value = (const float*)d_in[2];
    const int*   maskp = (const int*)  d_in[3];
    const float* Wq    = (const float*)d_in[4];
    const float* Wk    = (const float*)d_in[5];
    const float* Wv    = (const float*)d_in[6];
    float* out = (float*)d_out;

    cudaFuncSetAttribute(proj_mma, cudaFuncAttributeMaxDynamicSharedMemorySize,
                         (int)P_SMEM_BYTES);
    cudaFuncSetAttribute(attn_tc, cudaFuncAttributeMaxDynamicSharedMemorySize,
                         (int)A_SMEM_BYTES);

    proj_mma<<<dim3(NROWS / 128, 3), 256, P_SMEM_BYTES>>>(query, key, value, Wq, Wk, Wv);
    attn_tc<<<dim3(S_ / 128, B_), 256, A_SMEM_BYTES>>>(maskp, out);
}

// round 6
// speedup vs baseline: 4.8650x; 1.7185x over previous
#include <cuda_runtime.h>
#include <cuda_fp16.h>
#include <cstdint>
#include <math.h>

#define B_   8
#define S_   2048
#define MD   1024
#define DK   128
#define NROWS (B_*S_)

// projected q,k,v scratch (8.39 MB each)
__device__ float g_q[NROWS*DK];
__device__ float g_k[NROWS*DK];
__device__ float g_v[NROWS*DK];

// ===================== fp16 mma + split helpers =====================
__device__ __forceinline__ void mma_f16(float c[4],
                                        uint32_t a0, uint32_t a1, uint32_t a2, uint32_t a3,
                                        uint32_t b0, uint32_t b1)
{
    asm volatile("mma.sync.aligned.m16n8k16.row.col.f32.f16.f16.f32 "
                 "{%0,%1,%2,%3}, {%4,%5,%6,%7}, {%8,%9}, {%0,%1,%2,%3};"
                 : "+f"(c[0]), "+f"(c[1]), "+f"(c[2]), "+f"(c[3])
                 : "r"(a0), "r"(a1), "r"(a2), "r"(a3), "r"(b0), "r"(b1));
}

// split (x0,x1) into packed half2 hi (exact fp16 round) and lo (residual).
// half2 layout: .x (low 16 bits) = first element = lower k index.
__device__ __forceinline__ void split2h(float x0, float x1, uint32_t& hi, uint32_t& lo) {
    __half2 h = __floats2half2_rn(x0, x1);
    float2 f = __half22float2(h);
    __half2 l = __floats2half2_rn(x0 - f.x, x1 - f.y);
    hi = *reinterpret_cast<uint32_t*>(&h);
    lo = *reinterpret_cast<uint32_t*>(&l);
}

// ===================== projection: fp16 split-2 x3 tensor GEMM ====================
// Y[16384,128] = X[16384,1024] @ W[128,1024]^T
// CTA 128x128, 256 thr (8 warps 4x2), warp tile 32x64, K staged 32 at a time.
// smem: packed half2 hi/lo, u32 row stride 20 (16 data + 4 pad) -> conflict-free.

#define PJ_S  20
#define PJ_AH 0
#define PJ_AL 2560
#define PJ_BH 5120
#define PJ_BL 7680
#define PJ_SMEM_BYTES (10240 * 4)

__global__ __launch_bounds__(256) void proj_mma(
    const float* __restrict__ Xq, const float* __restrict__ Xk, const float* __restrict__ Xv,
    const float* __restrict__ Wq, const float* __restrict__ Wk, const float* __restrict__ Wv)
{
    const float* X; const float* W; float* Y;
    if (blockIdx.y == 0)      { X = Xq; W = Wq; Y = g_q; }
    else if (blockIdx.y == 1) { X = Xk; W = Wk; Y = g_k; }
    else                      { X = Xv; W = Wv; Y = g_v; }

    extern __shared__ uint32_t su[];

    const int tid  = threadIdx.x;
    const int wid  = tid >> 5, lane = tid & 31;
    const int wr   = wid >> 1, wc = wid & 1;
    const int rowt = lane >> 2;
    const int colt = lane & 3;
    const int row0 = blockIdx.x * 128;

    float acc[2][8][4];
    #pragma unroll
    for (int mt = 0; mt < 2; mt++)
        #pragma unroll
        for (int nt = 0; nt < 8; nt++)
            #pragma unroll
            for (int i = 0; i < 4; i++) acc[mt][nt][i] = 0.f;

    #pragma unroll 1
    for (int k0 = 0; k0 < MD; k0 += 32) {
        #pragma unroll
        for (int t = 0; t < 4; t++) {
            int idx = tid + t * 256;               // 0..1023 float4
            int row = idx >> 3, f4 = idx & 7;
            float4 a = *(const float4*)(X + (size_t)(row0 + row) * MD + k0 + f4 * 4);
            uint32_t h0, l0, h1, l1;
            split2h(a.x, a.y, h0, l0);
            split2h(a.z, a.w, h1, l1);
            *(uint2*)&su[PJ_AH + row * PJ_S + f4 * 2] = make_uint2(h0, h1);
            *(uint2*)&su[PJ_AL + row * PJ_S + f4 * 2] = make_uint2(l0, l1);

            float4 b = *(const float4*)(W + (size_t)row * MD + k0 + f4 * 4);
            split2h(b.x, b.y, h0, l0);
            split2h(b.z, b.w, h1, l1);
            *(uint2*)&su[PJ_BH + row * PJ_S + f4 * 2] = make_uint2(h0, h1);
            *(uint2*)&su[PJ_BL + row * PJ_S + f4 * 2] = make_uint2(l0, l1);
        }
        __syncthreads();

        #pragma unroll
        for (int c = 0; c < 2; c++) {              // two k16 chunks per stage
            const int co = c * 8;
            uint32_t ah[2][4], al[2][4];
            #pragma unroll
            for (int mt = 0; mt < 2; mt++) {
                int o0 = (wr * 32 + mt * 16 + rowt) * PJ_S + co + colt;
                int o1 = o0 + 8 * PJ_S;
                ah[mt][0] = su[PJ_AH + o0];  ah[mt][1] = su[PJ_AH + o1];
                ah[mt][2] = su[PJ_AH + o0 + 4];  ah[mt][3] = su[PJ_AH + o1 + 4];
                al[mt][0] = su[PJ_AL + o0];  al[mt][1] = su[PJ_AL + o1];
                al[mt][2] = su[PJ_AL + o0 + 4];  al[mt][3] = su[PJ_AL + o1 + 4];
            }
            #pragma unroll
            for (int nt = 0; nt < 8; nt++) {
                int ob = (wc * 64 + nt * 8 + rowt) * PJ_S + co + colt;
                uint32_t bh0 = su[PJ_BH + ob], bh1 = su[PJ_BH + ob + 4];
                uint32_t bl0 = su[PJ_BL + ob], bl1 = su[PJ_BL + ob + 4];
                #pragma unroll
                for (int mt = 0; mt < 2; mt++) {
                    mma_f16(acc[mt][nt], ah[mt][0], ah[mt][1], ah[mt][2], ah[mt][3], bh0, bh1);
                    mma_f16(acc[mt][nt], ah[mt][0], ah[mt][1], ah[mt][2], ah[mt][3], bl0, bl1);
                    mma_f16(acc[mt][nt], al[mt][0], al[mt][1], al[mt][2], al[mt][3], bh0, bh1);
                }
            }
        }
        __syncthreads();
    }

    #pragma unroll
    for (int mt = 0; mt < 2; mt++) {
        int gr = row0 + wr * 32 + mt * 16 + rowt;
        #pragma unroll
        for (int nt = 0; nt < 8; nt++) {
            int gc = wc * 64 + nt * 8 + colt * 2;
            float2 c01 = { acc[mt][nt][0], acc[mt][nt][1] };
            float2 c23 = { acc[mt][nt][2], acc[mt][nt][3] };
            *(float2*)(Y + (size_t)gr * DK + gc)       = c01;
            *(float2*)(Y + (size_t)(gr + 8) * DK + gc) = c23;
        }
    }
}

// ===================== fp16 tensor-core flash attention ===========================
// BQ=BK=128, 256 thr (8 warps 4x2), warp tile 32x64.
// smem (u32 units): packed half2 hi/lo for Q, K|V (shared), P + reduction scratch.
//   Q/K/P stride 68 (64+4): A/B frag banks 4*rowt+colt  -> conflict-free
//   V stride 136 (128+8), packed along k:  banks 8*colt+rowt -> conflict-free

#define AQ_S  68
#define AV_S  136
#define U_Q   0            // Qh @0, Ql @8704          (17408 u32)
#define U_KV  17408        // Kh/Vh @+0, Kl/Vl @+8704  (17408 u32)
#define U_P   34816        // Ph @+0, Pl @+8704        (17408 u32)
#define U_RM  52224        // redmax: 128 rows x 2 floats
#define U_RS  52480        // redsum: 128 rows x 2 floats
#define A_SMEM_BYTES ((52736) * 4)    // 210,944 B

__global__ __launch_bounds__(256) void attn_tc(const int* __restrict__ mask,
                                               float* __restrict__ out)
{
    extern __shared__ uint32_t su[];
    float* redm = (float*)&su[U_RM];
    float* reds = (float*)&su[U_RS];

    const int tid = threadIdx.x;
    const int wid = tid >> 5, lane = tid & 31;
    const int wr = wid >> 1, wc = wid & 1;
    const int rowt = lane >> 2, colt = lane & 3;
    const int qt = blockIdx.x, b = blockIdx.y;

    const float4* Qg = (const float4*)(g_q + ((size_t)b * S_ + (size_t)qt * 128) * DK);
    const float4* Kg = (const float4*)(g_k + (size_t)b * S_ * DK);
    const float4* Vg = (const float4*)(g_v + (size_t)b * S_ * DK);

    // ---- stage Q packed hi/lo ----
    #pragma unroll
    for (int t = 0; t < 16; t++) {
        int idx = tid + t * 256;                   // 0..4095 float4
        int row = idx >> 5, f4 = idx & 31;
        float4 q = Qg[idx];
        uint32_t h0, l0, h1, l1;
        split2h(q.x, q.y, h0, l0);
        split2h(q.z, q.w, h1, l1);
        *(uint2*)&su[U_Q + row * AQ_S + f4 * 2]        = make_uint2(h0, h1);
        *(uint2*)&su[U_Q + 8704 + row * AQ_S + f4 * 2] = make_uint2(l0, l1);
    }

    float acc[2][8][4];
    #pragma unroll
    for (int mt = 0; mt < 2; mt++)
        #pragma unroll
        for (int nt = 0; nt < 8; nt++)
            #pragma unroll
            for (int i = 0; i < 4; i++) acc[mt][nt][i] = 0.f;

    float mrow[4] = {-1e30f, -1e30f, -1e30f, -1e30f};
    float lrow[4] = {0.f, 0.f, 0.f, 0.f};
    const float scale = 0.08838834764831845f;      // 1/sqrt(128)

    #pragma unroll 1
    for (int kt = 0; kt < S_ / 128; kt++) {
        __syncthreads();                            // prev PV done with P/V
        // ---- stage K packed hi/lo ----
        const float4* Ksrc = Kg + (size_t)kt * 128 * 32;
        #pragma unroll
        for (int t = 0; t < 16; t++) {
            int idx = tid + t * 256;
            int row = idx >> 5, f4 = idx & 31;
            float4 k = Ksrc[idx];
            uint32_t h0, l0, h1, l1;
            split2h(k.x, k.y, h0, l0);
            split2h(k.z, k.w, h1, l1);
            *(uint2*)&su[U_KV + row * AQ_S + f4 * 2]        = make_uint2(h0, h1);
            *(uint2*)&su[U_KV + 8704 + row * AQ_S + f4 * 2] = make_uint2(l0, l1);
        }
        __syncthreads();

        // ---- S = Q K^T ----
        float s[2][8][4];
        #pragma unroll
        for (int mt = 0; mt < 2; mt++)
            #pragma unroll
            for (int nt = 0; nt < 8; nt++)
                #pragma unroll
                for (int i = 0; i < 4; i++) s[mt][nt][i] = 0.f;

        #pragma unroll 1
        for (int c = 0; c < 8; c++) {              // 8 k16 chunks
            const int co = c * 8;
            uint32_t ah[2][4], al[2][4];
            #pragma unroll
            for (int mt = 0; mt < 2; mt++) {
                int o0 = (wr * 32 + mt * 16 + rowt) * AQ_S + co + colt;
                int o1 = o0 + 8 * AQ_S;
                ah[mt][0] = su[U_Q + o0];      ah[mt][1] = su[U_Q + o1];
                ah[mt][2] = su[U_Q + o0 + 4];  ah[mt][3] = su[U_Q + o1 + 4];
                al[mt][0] = su[U_Q + 8704 + o0];      al[mt][1] = su[U_Q + 8704 + o1];
                al[mt][2] = su[U_Q + 8704 + o0 + 4];  al[mt][3] = su[U_Q + 8704 + o1 + 4];
            }
            #pragma unroll
            for (int nt = 0; nt < 8; nt++) {
                int ob = (wc * 64 + nt * 8 + rowt) * AQ_S + co + colt;
                uint32_t bh0 = su[U_KV + ob], bh1 = su[U_KV + ob + 4];
                uint32_t bl0 = su[U_KV + 8704 + ob], bl1 = su[U_KV + 8704 + ob + 4];
                #pragma unroll
                for (int mt = 0; mt < 2; mt++) {
                    mma_f16(s[mt][nt], ah[mt][0], ah[mt][1], ah[mt][2], ah[mt][3], bh0, bh1);
                    mma_f16(s[mt][nt], ah[mt][0], ah[mt][1], ah[mt][2], ah[mt][3], bl0, bl1);
                    mma_f16(s[mt][nt], al[mt][0], al[mt][1], al[mt][2], al[mt][3], bh0, bh1);
                }
            }
        }

        // ---- mask + scale in regs; per-warp partial row max ----
        const int* mbase = mask + ((size_t)b * S_ + (size_t)qt * 128) * S_ + (size_t)kt * 128
                                + wc * 64 + colt * 2;
        #pragma unroll
        for (int mt = 0; mt < 2; mt++) {
            int r0 = wr * 32 + mt * 16 + rowt;
            const int* m0p = mbase + (size_t)r0 * S_;
            const int* m1p = mbase + (size_t)(r0 + 8) * S_;
            float mx0 = -1e30f, mx1 = -1e30f;
            #pragma unroll
            for (int nt = 0; nt < 8; nt++) {
                int2 ma = *(const int2*)(m0p + nt * 8);
                int2 mb = *(const int2*)(m1p + nt * 8);
                s[mt][nt][0] = ma.x ? s[mt][nt][0] * scale : -1e9f;
                s[mt][nt][1] = ma.y ? s[mt][nt][1] * scale : -1e9f;
                s[mt][nt][2] = mb.x ? s[mt][nt][2] * scale : -1e9f;
                s[mt][nt][3] = mb.y ? s[mt][nt][3] * scale : -1e9f;
                mx0 = fmaxf(mx0, fmaxf(s[mt][nt][0], s[mt][nt][1]));
                mx1 = fmaxf(mx1, fmaxf(s[mt][nt][2], s[mt][nt][3]));
            }
            mx0 = fmaxf(mx0, __shfl_xor_sync(0xffffffffu, mx0, 1));
            mx0 = fmaxf(mx0, __shfl_xor_sync(0xffffffffu, mx0, 2));
            mx1 = fmaxf(mx1, __shfl_xor_sync(0xffffffffu, mx1, 1));
            mx1 = fmaxf(mx1, __shfl_xor_sync(0xffffffffu, mx1, 2));
            if (colt == 0) {
                redm[r0 * 2 + wc]       = mx0;
                redm[(r0 + 8) * 2 + wc] = mx1;
            }
        }
        __syncthreads();   // K reads done by all warps; max partials visible

        // ---- stage V packed-along-k hi/lo (over K buffer) ----
        const float4* Vsrc = Vg + (size_t)kt * 128 * 32;
        #pragma unroll
        for (int t = 0; t < 8; t++) {
            int idx = tid + t * 256;               // 0..2047
            int kp = idx >> 5, n4 = idx & 31;
            float4 va = Vsrc[(size_t)(2 * kp) * 32 + n4];
            float4 vb = Vsrc[(size_t)(2 * kp + 1) * 32 + n4];
            uint32_t h[4], l[4];
            split2h(va.x, vb.x, h[0], l[0]);
            split2h(va.y, vb.y, h[1], l[1]);
            split2h(va.z, vb.z, h[2], l[2]);
            split2h(va.w, vb.w, h[3], l[3]);
            *(uint4*)&su[U_KV + kp * AV_S + n4 * 4]        = make_uint4(h[0], h[1], h[2], h[3]);
            *(uint4*)&su[U_KV + 8704 + kp * AV_S + n4 * 4] = make_uint4(l[0], l[1], l[2], l[3]);
        }

        // ---- softmax: m/corr, exp, partial sums, rescale acc, write packed P ----
        float crr[4];
        #pragma unroll
        for (int mt = 0; mt < 2; mt++) {
            int r0 = wr * 32 + mt * 16 + rowt;
            int r1 = r0 + 8;
            float mn0 = fmaxf(mrow[mt*2],   fmaxf(redm[r0 * 2], redm[r0 * 2 + 1]));
            float mn1 = fmaxf(mrow[mt*2+1], fmaxf(redm[r1 * 2], redm[r1 * 2 + 1]));
            crr[mt*2]   = __expf(mrow[mt*2]   - mn0);
            crr[mt*2+1] = __expf(mrow[mt*2+1] - mn1);
            mrow[mt*2] = mn0;  mrow[mt*2+1] = mn1;
            float sm0 = 0.f, sm1 = 0.f;
            #pragma unroll
            for (int nt = 0; nt < 8; nt++) {
                float p0 = __expf(s[mt][nt][0] - mn0);
                float p1 = __expf(s[mt][nt][1] - mn0);
                float p2 = __expf(s[mt][nt][2] - mn1);
                float p3 = __expf(s[mt][nt][3] - mn1);
                sm0 += p0 + p1;  sm1 += p2 + p3;
                uint32_t h0, l0, h1, l1;
                split2h(p0, p1, h0, l0);
                split2h(p2, p3, h1, l1);
                int pc = wc * 32 + nt * 4 + colt;
                su[U_P + r0 * AQ_S + pc]        = h0;
                su[U_P + 8704 + r0 * AQ_S + pc] = l0;
                su[U_P + r1 * AQ_S + pc]        = h1;
                su[U_P + 8704 + r1 * AQ_S + pc] = l1;
                // rescale acc
                acc[mt][nt][0] *= crr[mt*2];   acc[mt][nt][1] *= crr[mt*2];
                acc[mt][nt][2] *= crr[mt*2+1]; acc[mt][nt][3] *= crr[mt*2+1];
            }
            sm0 += __shfl_xor_sync(0xffffffffu, sm0, 1);
            sm0 += __shfl_xor_sync(0xffffffffu, sm0, 2);
            sm1 += __shfl_xor_sync(0xffffffffu, sm1, 1);
            sm1 += __shfl_xor_sync(0xffffffffu, sm1, 2);
            if (colt == 0) {
                reds[r0 * 2 + wc] = sm0;
                reds[r1 * 2 + wc] = sm1;
            }
        }
        __syncthreads();   // P + sum partials visible; V staged

        // ---- update l (replicated in regs) ----
        #pragma unroll
        for (int mt = 0; mt < 2; mt++) {
            int r0 = wr * 32 + mt * 16 + rowt;
            int r1 = r0 + 8;
            lrow[mt*2]   = lrow[mt*2]   * crr[mt*2]   + reds[r0 * 2] + reds[r0 * 2 + 1];
            lrow[mt*2+1] = lrow[mt*2+1] * crr[mt*2+1] + reds[r1 * 2] + reds[r1 * 2 + 1];
        }

        // ---- acc += P V ----
        #pragma unroll 1
        for (int c = 0; c < 8; c++) {
            const int co = c * 8;
            uint32_t ah[2][4], al[2][4];
            #pragma unroll
            for (int mt = 0; mt < 2; mt++) {
                int o0 = (wr * 32 + mt * 16 + rowt) * AQ_S + co + colt;
                int o1 = o0 + 8 * AQ_S;
                ah[mt][0] = su[U_P + o0];      ah[mt][1] = su[U_P + o1];
                ah[mt][2] = su[U_P + o0 + 4];  ah[mt][3] = su[U_P + o1 + 4];
                al[mt][0] = su[U_P + 8704 + o0];      al[mt][1] = su[U_P + 8704 + o1];
                al[mt][2] = su[U_P + 8704 + o0 + 4];  al[mt][3] = su[U_P + 8704 + o1 + 4];
            }
            #pragma unroll
            for (int nt = 0; nt < 8; nt++) {
                int ob = (co + colt) * AV_S + wc * 64 + nt * 8 + rowt;
                uint32_t bh0 = su[U_KV + ob], bh1 = su[U_KV + ob + 4 * AV_S];
                uint32_t bl0 = su[U_KV + 8704 + ob], bl1 = su[U_KV + 8704 + ob + 4 * AV_S];
                #pragma unroll
                for (int mt = 0; mt < 2; mt++) {
                    mma_f16(acc[mt][nt], ah[mt][0], ah[mt][1], ah[mt][2], ah[mt][3], bh0, bh1);
                    mma_f16(acc[mt][nt], ah[mt][0], ah[mt][1], ah[mt][2], ah[mt][3], bl0, bl1);
                    mma_f16(acc[mt][nt], al[mt][0], al[mt][1], al[mt][2], al[mt][3], bh0, bh1);
                }
            }
        }
    }

    // ---- epilogue ----
    #pragma unroll
    for (int mt = 0; mt < 2; mt++) {
        int r0 = wr * 32 + mt * 16 + rowt;
        float il0 = 1.f / lrow[mt*2];
        float il1 = 1.f / lrow[mt*2+1];
        size_t gr = (size_t)b * S_ + (size_t)qt * 128 + r0;
        #pragma unroll
        for (int nt = 0; nt < 8; nt++) {
            int c0 = wc * 64 + nt * 8 + colt * 2;
            float2 o0 = { acc[mt][nt][0] * il0, acc[mt][nt][1] * il0 };
            float2 o1 = { acc[mt][nt][2] * il1, acc[mt][nt][3] * il1 };
            *(float2*)(out + gr * DK + c0)       = o0;
            *(float2*)(out + (gr + 8) * DK + c0) = o1;
        }
    }
}

// ===================== launch =====================
extern "C" void kernel_launch(void* const* d_in, const int* in_sizes, int n_in,
                              void* d_out, int out_size)
{
    const float* query = (const float*)d_in[0];
    const float* key   = (const float*)d_in[1];
    const float* value = (const float*)d_in[2];
    const int*   maskp = (const int*)  d_in[3];
    const float* Wq    = (const float*)d_in[4];
    const float* Wk    = (const float*)d_in[5];
    const float* Wv    = (const float*)d_in[6];
    float* out = (float*)d_out;

    cudaFuncSetAttribute(proj_mma, cudaFuncAttributeMaxDynamicSharedMemorySize,
                         (int)PJ_SMEM_BYTES);
    cudaFuncSetAttribute(attn_tc, cudaFuncAttributeMaxDynamicSharedMemorySize,
                         (int)A_SMEM_BYTES);

    proj_mma<<<dim3(NROWS / 128, 3), 256, PJ_SMEM_BYTES>>>(query, key, value, Wq, Wk, Wv);
    attn_tc<<<dim3(S_ / 128, B_), 256, A_SMEM_BYTES>>>(maskp, out);
}

// round 7
// speedup vs baseline: 5.3771x; 1.1052x over previous
#include <cuda_runtime.h>
#include <cuda_fp16.h>
#include <cstdint>
#include <math.h>

#define B_   8
#define S_   2048
#define MD   1024
#define DK   128
#define NROWS (B_*S_)

// projected q,k,v scratch (8.39 MB each)
__device__ float g_q[NROWS*DK];
__device__ float g_k[NROWS*DK];
__device__ float g_v[NROWS*DK];

// ===================== fp16 mma + split helpers =====================
__device__ __forceinline__ void mma_f16(float c[4],
                                        uint32_t a0, uint32_t a1, uint32_t a2, uint32_t a3,
                                        uint32_t b0, uint32_t b1)
{
    asm volatile("mma.sync.aligned.m16n8k16.row.col.f32.f16.f16.f32 "
                 "{%0,%1,%2,%3}, {%4,%5,%6,%7}, {%8,%9}, {%0,%1,%2,%3};"
                 : "+f"(c[0]), "+f"(c[1]), "+f"(c[2]), "+f"(c[3])
                 : "r"(a0), "r"(a1), "r"(a2), "r"(a3), "r"(b0), "r"(b1));
}

// split (x0,x1) into packed half2 hi (exact fp16 round) and lo (residual)
__device__ __forceinline__ void split2h(float x0, float x1, uint32_t& hi, uint32_t& lo) {
    __half2 h = __floats2half2_rn(x0, x1);
    float2 f = __half22float2(h);
    __half2 l = __floats2half2_rn(x0 - f.x, x1 - f.y);
    hi = *reinterpret_cast<uint32_t*>(&h);
    lo = *reinterpret_cast<uint32_t*>(&l);
}

// ===================== projection: fp16 split, 512 thr, K-stage 64 ================
// Y[16384,128] = X[16384,1024] @ W[128,1024]^T
// CTA 128x128, 16 warps (4x4), warp tile 32x32.

#define PJ_S  36                     // u32 row stride (32 data + 4 pad)
#define PJ_AH 0
#define PJ_AL 4608
#define PJ_BH 9216
#define PJ_BL 13824
#define PJ_SMEM_BYTES (18432 * 4)    // 73,728 B

__global__ __launch_bounds__(512) void proj_mma(
    const float* __restrict__ Xq, const float* __restrict__ Xk, const float* __restrict__ Xv,
    const float* __restrict__ Wq, const float* __restrict__ Wk, const float* __restrict__ Wv)
{
    const float* X; const float* W; float* Y;
    if (blockIdx.y == 0)      { X = Xq; W = Wq; Y = g_q; }
    else if (blockIdx.y == 1) { X = Xk; W = Wk; Y = g_k; }
    else                      { X = Xv; W = Wv; Y = g_v; }

    extern __shared__ uint32_t su[];

    const int tid  = threadIdx.x;
    const int wid  = tid >> 5, lane = tid & 31;
    const int wr   = wid >> 2, wc = wid & 3;       // 4x4 warp grid
    const int rowt = lane >> 2;
    const int colt = lane & 3;
    const int row0 = blockIdx.x * 128;

    float acc[2][4][4];
    #pragma unroll
    for (int mt = 0; mt < 2; mt++)
        #pragma unroll
        for (int nt = 0; nt < 4; nt++)
            #pragma unroll
            for (int i = 0; i < 4; i++) acc[mt][nt][i] = 0.f;

    #pragma unroll 1
    for (int k0 = 0; k0 < MD; k0 += 64) {
        // ---- stage A (128x64) + B (128x64), packed half2 hi/lo ----
        #pragma unroll
        for (int t = 0; t < 4; t++) {
            int idx = tid + t * 512;               // 0..2047 float4
            int row = idx >> 4, f4 = idx & 15;
            float4 a = *(const float4*)(X + (size_t)(row0 + row) * MD + k0 + f4 * 4);
            uint32_t h0, l0, h1, l1;
            split2h(a.x, a.y, h0, l0);
            split2h(a.z, a.w, h1, l1);
            *(uint2*)&su[PJ_AH + row * PJ_S + f4 * 2] = make_uint2(h0, h1);
            *(uint2*)&su[PJ_AL + row * PJ_S + f4 * 2] = make_uint2(l0, l1);

            float4 b = *(const float4*)(W + (size_t)row * MD + k0 + f4 * 4);
            split2h(b.x, b.y, h0, l0);
            split2h(b.z, b.w, h1, l1);
            *(uint2*)&su[PJ_BH + row * PJ_S + f4 * 2] = make_uint2(h0, h1);
            *(uint2*)&su[PJ_BL + row * PJ_S + f4 * 2] = make_uint2(l0, l1);
        }
        __syncthreads();

        #pragma unroll
        for (int c = 0; c < 4; c++) {              // four k16 chunks per stage
            const int co = c * 8;
            uint32_t ah[2][4], al[2][4];
            #pragma unroll
            for (int mt = 0; mt < 2; mt++) {
                int o0 = (wr * 32 + mt * 16 + rowt) * PJ_S + co + colt;
                int o1 = o0 + 8 * PJ_S;
                ah[mt][0] = su[PJ_AH + o0];      ah[mt][1] = su[PJ_AH + o1];
                ah[mt][2] = su[PJ_AH + o0 + 4];  ah[mt][3] = su[PJ_AH + o1 + 4];
                al[mt][0] = su[PJ_AL + o0];      al[mt][1] = su[PJ_AL + o1];
                al[mt][2] = su[PJ_AL + o0 + 4];  al[mt][3] = su[PJ_AL + o1 + 4];
            }
            #pragma unroll
            for (int nt = 0; nt < 4; nt++) {
                int ob = (wc * 32 + nt * 8 + rowt) * PJ_S + co + colt;
                uint32_t bh0 = su[PJ_BH + ob], bh1 = su[PJ_BH + ob + 4];
                uint32_t bl0 = su[PJ_BL + ob], bl1 = su[PJ_BL + ob + 4];
                #pragma unroll
                for (int mt = 0; mt < 2; mt++) {
                    mma_f16(acc[mt][nt], ah[mt][0], ah[mt][1], ah[mt][2], ah[mt][3], bh0, bh1);
                    mma_f16(acc[mt][nt], ah[mt][0], ah[mt][1], ah[mt][2], ah[mt][3], bl0, bl1);
                    mma_f16(acc[mt][nt], al[mt][0], al[mt][1], al[mt][2], al[mt][3], bh0, bh1);
                }
            }
        }
        __syncthreads();
    }

    #pragma unroll
    for (int mt = 0; mt < 2; mt++) {
        int gr = row0 + wr * 32 + mt * 16 + rowt;
        #pragma unroll
        for (int nt = 0; nt < 4; nt++) {
            int gc = wc * 32 + nt * 8 + colt * 2;
            float2 c01 = { acc[mt][nt][0], acc[mt][nt][1] };
            float2 c23 = { acc[mt][nt][2], acc[mt][nt][3] };
            *(float2*)(Y + (size_t)gr * DK + gc)       = c01;
            *(float2*)(Y + (size_t)(gr + 8) * DK + gc) = c23;
        }
    }
}

// ===================== fp16 tensor-core flash attention, 512 thr ==================
// BQ=BK=128, 16 warps (4x4), warp tile 32x32.

#define AQ_S  68
#define AV_S  136
#define U_Q   0            // Qh @0, Ql @8704          (17408 u32)
#define U_KV  17408        // Kh/Vh @+0, Kl/Vl @+8704  (17408 u32)
#define U_P   34816        // Ph @+0, Pl @+8704        (17408 u32)
#define U_RM  52224        // redmax: 128 rows x 4 partials
#define U_RS  52736        // redsum: 128 rows x 4 partials
#define A_SMEM_BYTES ((53248) * 4)    // 212,992 B

__global__ __launch_bounds__(512) void attn_tc(const int* __restrict__ mask,
                                               float* __restrict__ out)
{
    extern __shared__ uint32_t su[];
    float* redm = (float*)&su[U_RM];
    float* reds = (float*)&su[U_RS];

    const int tid = threadIdx.x;
    const int wid = tid >> 5, lane = tid & 31;
    const int wr = wid >> 2, wc = wid & 3;         // 4x4 warp grid
    const int rowt = lane >> 2, colt = lane & 3;
    const int qt = blockIdx.x, b = blockIdx.y;

    const float4* Qg = (const float4*)(g_q + ((size_t)b * S_ + (size_t)qt * 128) * DK);
    const float4* Kg = (const float4*)(g_k + (size_t)b * S_ * DK);
    const float4* Vg = (const float4*)(g_v + (size_t)b * S_ * DK);

    // ---- stage Q packed hi/lo ----
    #pragma unroll
    for (int t = 0; t < 8; t++) {
        int idx = tid + t * 512;                   // 0..4095 float4
        int row = idx >> 5, f4 = idx & 31;
        float4 q = Qg[idx];
        uint32_t h0, l0, h1, l1;
        split2h(q.x, q.y, h0, l0);
        split2h(q.z, q.w, h1, l1);
        *(uint2*)&su[U_Q + row * AQ_S + f4 * 2]        = make_uint2(h0, h1);
        *(uint2*)&su[U_Q + 8704 + row * AQ_S + f4 * 2] = make_uint2(l0, l1);
    }

    float acc[2][4][4];
    #pragma unroll
    for (int mt = 0; mt < 2; mt++)
        #pragma unroll
        for (int nt = 0; nt < 4; nt++)
            #pragma unroll
            for (int i = 0; i < 4; i++) acc[mt][nt][i] = 0.f;

    float mrow[4] = {-1e30f, -1e30f, -1e30f, -1e30f};
    float lrow[4] = {0.f, 0.f, 0.f, 0.f};
    const float scale = 0.08838834764831845f;      // 1/sqrt(128)

    #pragma unroll 1
    for (int kt = 0; kt < S_ / 128; kt++) {
        __syncthreads();                            // prev PV done with P/V
        // ---- stage K packed hi/lo ----
        const float4* Ksrc = Kg + (size_t)kt * 128 * 32;
        #pragma unroll
        for (int t = 0; t < 8; t++) {
            int idx = tid + t * 512;
            int row = idx >> 5, f4 = idx & 31;
            float4 k = Ksrc[idx];
            uint32_t h0, l0, h1, l1;
            split2h(k.x, k.y, h0, l0);
            split2h(k.z, k.w, h1, l1);
            *(uint2*)&su[U_KV + row * AQ_S + f4 * 2]        = make_uint2(h0, h1);
            *(uint2*)&su[U_KV + 8704 + row * AQ_S + f4 * 2] = make_uint2(l0, l1);
        }
        __syncthreads();

        // ---- S = Q K^T ----
        float s[2][4][4];
        #pragma unroll
        for (int mt = 0; mt < 2; mt++)
            #pragma unroll
            for (int nt = 0; nt < 4; nt++)
                #pragma unroll
                for (int i = 0; i < 4; i++) s[mt][nt][i] = 0.f;

        #pragma unroll 1
        for (int c = 0; c < 8; c++) {              // 8 k16 chunks
            const int co = c * 8;
            uint32_t ah[2][4], al[2][4];
            #pragma unroll
            for (int mt = 0; mt < 2; mt++) {
                int o0 = (wr * 32 + mt * 16 + rowt) * AQ_S + co + colt;
                int o1 = o0 + 8 * AQ_S;
                ah[mt][0] = su[U_Q + o0];      ah[mt][1] = su[U_Q + o1];
                ah[mt][2] = su[U_Q + o0 + 4];  ah[mt][3] = su[U_Q + o1 + 4];
                al[mt][0] = su[U_Q + 8704 + o0];      al[mt][1] = su[U_Q + 8704 + o1];
                al[mt][2] = su[U_Q + 8704 + o0 + 4];  al[mt][3] = su[U_Q + 8704 + o1 + 4];
            }
            #pragma unroll
            for (int nt = 0; nt < 4; nt++) {
                int ob = (wc * 32 + nt * 8 + rowt) * AQ_S + co + colt;
                uint32_t bh0 = su[U_KV + ob], bh1 = su[U_KV + ob + 4];
                uint32_t bl0 = su[U_KV + 8704 + ob], bl1 = su[U_KV + 8704 + ob + 4];
                #pragma unroll
                for (int mt = 0; mt < 2; mt++) {
                    mma_f16(s[mt][nt], ah[mt][0], ah[mt][1], ah[mt][2], ah[mt][3], bh0, bh1);
                    mma_f16(s[mt][nt], ah[mt][0], ah[mt][1], ah[mt][2], ah[mt][3], bl0, bl1);
                    mma_f16(s[mt][nt], al[mt][0], al[mt][1], al[mt][2], al[mt][3], bh0, bh1);
                }
            }
        }

        // ---- mask + scale in regs; per-warp partial row max ----
        const int* mbase = mask + ((size_t)b * S_ + (size_t)qt * 128) * S_ + (size_t)kt * 128
                                + wc * 32 + colt * 2;
        #pragma unroll
        for (int mt = 0; mt < 2; mt++) {
            int r0 = wr * 32 + mt * 16 + rowt;
            const int* m0p = mbase + (size_t)r0 * S_;
            const int* m1p = mbase + (size_t)(r0 + 8) * S_;
            float mx0 = -1e30f, mx1 = -1e30f;
            #pragma unroll
            for (int nt = 0; nt < 4; nt++) {
                int2 ma = *(const int2*)(m0p + nt * 8);
                int2 mb = *(const int2*)(m1p + nt * 8);
                s[mt][nt][0] = ma.x ? s[mt][nt][0] * scale : -1e9f;
                s[mt][nt][1] = ma.y ? s[mt][nt][1] * scale : -1e9f;
                s[mt][nt][2] = mb.x ? s[mt][nt][2] * scale : -1e9f;
                s[mt][nt][3] = mb.y ? s[mt][nt][3] * scale : -1e9f;
                mx0 = fmaxf(mx0, fmaxf(s[mt][nt][0], s[mt][nt][1]));
                mx1 = fmaxf(mx1, fmaxf(s[mt][nt][2], s[mt][nt][3]));
            }
            mx0 = fmaxf(mx0, __shfl_xor_sync(0xffffffffu, mx0, 1));
            mx0 = fmaxf(mx0, __shfl_xor_sync(0xffffffffu, mx0, 2));
            mx1 = fmaxf(mx1, __shfl_xor_sync(0xffffffffu, mx1, 1));
            mx1 = fmaxf(mx1, __shfl_xor_sync(0xffffffffu, mx1, 2));
            if (colt == 0) {
                redm[r0 * 4 + wc]       = mx0;
                redm[(r0 + 8) * 4 + wc] = mx1;
            }
        }
        __syncthreads();   // K reads done; max partials visible

        // ---- stage V packed-along-k hi/lo (over K buffer) ----
        const float4* Vsrc = Vg + (size_t)kt * 128 * 32;
        #pragma unroll
        for (int t = 0; t < 4; t++) {
            int idx = tid + t * 512;               // 0..2047
            int kp = idx >> 5, n4 = idx & 31;
            float4 va = Vsrc[(size_t)(2 * kp) * 32 + n4];
            float4 vb = Vsrc[(size_t)(2 * kp + 1) * 32 + n4];
            uint32_t h[4], l[4];
            split2h(va.x, vb.x, h[0], l[0]);
            split2h(va.y, vb.y, h[1], l[1]);
            split2h(va.z, vb.z, h[2], l[2]);
            split2h(va.w, vb.w, h[3], l[3]);
            *(uint4*)&su[U_KV + kp * AV_S + n4 * 4]        = make_uint4(h[0], h[1], h[2], h[3]);
            *(uint4*)&su[U_KV + 8704 + kp * AV_S + n4 * 4] = make_uint4(l[0], l[1], l[2], l[3]);
        }

        // ---- softmax: m/corr, exp, partial sums, rescale acc, write packed P ----
        float crr[4];
        #pragma unroll
        for (int mt = 0; mt < 2; mt++) {
            int r0 = wr * 32 + mt * 16 + rowt;
            int r1 = r0 + 8;
            float mn0 = fmaxf(fmaxf(redm[r0 * 4], redm[r0 * 4 + 1]),
                              fmaxf(redm[r0 * 4 + 2], redm[r0 * 4 + 3]));
            float mn1 = fmaxf(fmaxf(redm[r1 * 4], redm[r1 * 4 + 1]),
                              fmaxf(redm[r1 * 4 + 2], redm[r1 * 4 + 3]));
            mn0 = fmaxf(mrow[mt*2], mn0);
            mn1 = fmaxf(mrow[mt*2+1], mn1);
            crr[mt*2]   = __expf(mrow[mt*2]   - mn0);
            crr[mt*2+1] = __expf(mrow[mt*2+1] - mn1);
            mrow[mt*2] = mn0;  mrow[mt*2+1] = mn1;
            float sm0 = 0.f, sm1 = 0.f;
            #pragma unroll
            for (int nt = 0; nt < 4; nt++) {
                float p0 = __expf(s[mt][nt][0] - mn0);
                float p1 = __expf(s[mt][nt][1] - mn0);
                float p2 = __expf(s[mt][nt][2] - mn1);
                float p3 = __expf(s[mt][nt][3] - mn1);
                sm0 += p0 + p1;  sm1 += p2 + p3;
                uint32_t h0, l0, h1, l1;
                split2h(p0, p1, h0, l0);
                split2h(p2, p3, h1, l1);
                int pc = wc * 16 + nt * 4 + colt;
                su[U_P + r0 * AQ_S + pc]        = h0;
                su[U_P + 8704 + r0 * AQ_S + pc] = l0;
                su[U_P + r1 * AQ_S + pc]        = h1;
                su[U_P + 8704 + r1 * AQ_S + pc] = l1;
                acc[mt][nt][0] *= crr[mt*2];   acc[mt][nt][1] *= crr[mt*2];
                acc[mt][nt][2] *= crr[mt*2+1]; acc[mt][nt][3] *= crr[mt*2+1];
            }
            sm0 += __shfl_xor_sync(0xffffffffu, sm0, 1);
            sm0 += __shfl_xor_sync(0xffffffffu, sm0, 2);
            sm1 += __shfl_xor_sync(0xffffffffu, sm1, 1);
            sm1 += __shfl_xor_sync(0xffffffffu, sm1, 2);
            if (colt == 0) {
                reds[r0 * 4 + wc] = sm0;
                reds[r1 * 4 + wc] = sm1;
            }
        }
        __syncthreads();   // P + sum partials visible; V staged

        // ---- update l ----
        #pragma unroll
        for (int mt = 0; mt < 2; mt++) {
            int r0 = wr * 32 + mt * 16 + rowt;
            int r1 = r0 + 8;
            lrow[mt*2]   = lrow[mt*2]   * crr[mt*2]
                         + reds[r0*4] + reds[r0*4+1] + reds[r0*4+2] + reds[r0*4+3];
            lrow[mt*2+1] = lrow[mt*2+1] * crr[mt*2+1]
                         + reds[r1*4] + reds[r1*4+1] + reds[r1*4+2] + reds[r1*4+3];
        }

        // ---- acc += P V ----
        #pragma unroll 1
        for (int c = 0; c < 8; c++) {
            const int co = c * 8;
            uint32_t ah[2][4], al[2][4];
            #pragma unroll
            for (int mt = 0; mt < 2; mt++) {
                int o0 = (wr * 32 + mt * 16 + rowt) * AQ_S + co + colt;
                int o1 = o0 + 8 * AQ_S;
                ah[mt][0] = su[U_P + o0];      ah[mt][1] = su[U_P + o1];
                ah[mt][2] = su[U_P + o0 + 4];  ah[mt][3] = su[U_P + o1 + 4];
                al[mt][0] = su[U_P + 8704 + o0];      al[mt][1] = su[U_P + 8704 + o1];
                al[mt][2] = su[U_P + 8704 + o0 + 4];  al[mt][3] = su[U_P + 8704 + o1 + 4];
            }
            #pragma unroll
            for (int nt = 0; nt < 4; nt++) {
                int ob = (co + colt) * AV_S + wc * 32 + nt * 8 + rowt;
                uint32_t bh0 = su[U_KV + ob], bh1 = su[U_KV + ob + 4 * AV_S];
                uint32_t bl0 = su[U_KV + 8704 + ob], bl1 = su[U_KV + 8704 + ob + 4 * AV_S];
                #pragma unroll
                for (int mt = 0; mt < 2; mt++) {
                    mma_f16(acc[mt][nt], ah[mt][0], ah[mt][1], ah[mt][2], ah[mt][3], bh0, bh1);
                    mma_f16(acc[mt][nt], ah[mt][0], ah[mt][1], ah[mt][2], ah[mt][3], bl0, bl1);
                    mma_f16(acc[mt][nt], al[mt][0], al[mt][1], al[mt][2], al[mt][3], bh0, bh1);
                }
            }
        }
    }

    // ---- epilogue ----
    #pragma unroll
    for (int mt = 0; mt < 2; mt++) {
        int r0 = wr * 32 + mt * 16 + rowt;
        float il0 = 1.f / lrow[mt*2];
        float il1 = 1.f / lrow[mt*2+1];
        size_t gr = (size_t)b * S_ + (size_t)qt * 128 + r0;
        #pragma unroll
        for (int nt = 0; nt < 4; nt++) {
            int c0 = wc * 32 + nt * 8 + colt * 2;
            float2 o0 = { acc[mt][nt][0] * il0, acc[mt][nt][1] * il0 };
            float2 o1 = { acc[mt][nt][2] * il1, acc[mt][nt][3] * il1 };
            *(float2*)(out + gr * DK + c0)       = o0;
            *(float2*)(out + (gr + 8) * DK + c0) = o1;
        }
    }
}

// ===================== launch =====================
extern "C" void kernel_launch(void* const* d_in, const int* in_sizes, int n_in,
                              void* d_out, int out_size)
{
    const float* query = (const float*)d_in[0];
    const float* key   = (const float*)d_in[1];
    const float* value = (const float*)d_in[2];
    const int*   maskp = (const int*)  d_in[3];
    const float* Wq    = (const float*)d_in[4];
    const float* Wk    = (const float*)d_in[5];
    const float* Wv    = (const float*)d_in[6];
    float* out = (float*)d_out;

    cudaFuncSetAttribute(proj_mma, cudaFuncAttributeMaxDynamicSharedMemorySize,
                         (int)PJ_SMEM_BYTES);
    cudaFuncSetAttribute(attn_tc, cudaFuncAttributeMaxDynamicSharedMemorySize,
                         (int)A_SMEM_BYTES);

    proj_mma<<<dim3(NROWS / 128, 3), 512, PJ_SMEM_BYTES>>>(query, key, value, Wq, Wk, Wv);
    attn_tc<<<dim3(S_ / 128, B_), 512, A_SMEM_BYTES>>>(maskp, out);
}

// round 8
// speedup vs baseline: 5.9527x; 1.1070x over previous
#include <cuda_runtime.h>
#include <cuda_fp16.h>
#include <cstdint>
#include <math.h>

#define B_   8
#define S_   2048
#define MD   1024
#define DK   128
#define NROWS (B_*S_)

// projected q,k,v scratch (8.39 MB each)
__device__ float g_q[NROWS*DK];
__device__ float g_k[NROWS*DK];
__device__ float g_v[NROWS*DK];

// ===================== fp16 mma + split helpers =====================
__device__ __forceinline__ void mma_f16(float c[4],
                                        uint32_t a0, uint32_t a1, uint32_t a2, uint32_t a3,
                                        uint32_t b0, uint32_t b1)
{
    asm volatile("mma.sync.aligned.m16n8k16.row.col.f32.f16.f16.f32 "
                 "{%0,%1,%2,%3}, {%4,%5,%6,%7}, {%8,%9}, {%0,%1,%2,%3};"
                 : "+f"(c[0]), "+f"(c[1]), "+f"(c[2]), "+f"(c[3])
                 : "r"(a0), "r"(a1), "r"(a2), "r"(a3), "r"(b0), "r"(b1));
}

// split (x0,x1) into packed half2 hi (exact fp16 round) and lo (residual)
__device__ __forceinline__ void split2h(float x0, float x1, uint32_t& hi, uint32_t& lo) {
    __half2 h = __floats2half2_rn(x0, x1);
    float2 f = __half22float2(h);
    __half2 l = __floats2half2_rn(x0 - f.x, x1 - f.y);
    hi = *reinterpret_cast<uint32_t*>(&h);
    lo = *reinterpret_cast<uint32_t*>(&l);
}

__device__ __forceinline__ uint32_t pack2h(float x0, float x1) {
    __half2 h = __floats2half2_rn(x0, x1);
    return *reinterpret_cast<uint32_t*>(&h);
}

// ===================== projection: fp16 split, 512 thr, K-stage 64 ================
#define PJ_S  36
#define PJ_AH 0
#define PJ_AL 4608
#define PJ_BH 9216
#define PJ_BL 13824
#define PJ_SMEM_BYTES (18432 * 4)

__global__ __launch_bounds__(512) void proj_mma(
    const float* __restrict__ Xq, const float* __restrict__ Xk, const float* __restrict__ Xv,
    const float* __restrict__ Wq, const float* __restrict__ Wk, const float* __restrict__ Wv)
{
    const float* X; const float* W; float* Y;
    if (blockIdx.y == 0)      { X = Xq; W = Wq; Y = g_q; }
    else if (blockIdx.y == 1) { X = Xk; W = Wk; Y = g_k; }
    else                      { X = Xv; W = Wv; Y = g_v; }

    extern __shared__ uint32_t su[];

    const int tid  = threadIdx.x;
    const int wid  = tid >> 5, lane = tid & 31;
    const int wr   = wid >> 2, wc = wid & 3;
    const int rowt = lane >> 2;
    const int colt = lane & 3;
    const int row0 = blockIdx.x * 128;

    float acc[2][4][4];
    #pragma unroll
    for (int mt = 0; mt < 2; mt++)
        #pragma unroll
        for (int nt = 0; nt < 4; nt++)
            #pragma unroll
            for (int i = 0; i < 4; i++) acc[mt][nt][i] = 0.f;

    #pragma unroll 1
    for (int k0 = 0; k0 < MD; k0 += 64) {
        #pragma unroll
        for (int t = 0; t < 4; t++) {
            int idx = tid + t * 512;
            int row = idx >> 4, f4 = idx & 15;
            float4 a = *(const float4*)(X + (size_t)(row0 + row) * MD + k0 + f4 * 4);
            uint32_t h0, l0, h1, l1;
            split2h(a.x, a.y, h0, l0);
            split2h(a.z, a.w, h1, l1);
            *(uint2*)&su[PJ_AH + row * PJ_S + f4 * 2] = make_uint2(h0, h1);
            *(uint2*)&su[PJ_AL + row * PJ_S + f4 * 2] = make_uint2(l0, l1);

            float4 b = *(const float4*)(W + (size_t)row * MD + k0 + f4 * 4);
            split2h(b.x, b.y, h0, l0);
            split2h(b.z, b.w, h1, l1);
            *(uint2*)&su[PJ_BH + row * PJ_S + f4 * 2] = make_uint2(h0, h1);
            *(uint2*)&su[PJ_BL + row * PJ_S + f4 * 2] = make_uint2(l0, l1);
        }
        __syncthreads();

        #pragma unroll
        for (int c = 0; c < 4; c++) {
            const int co = c * 8;
            uint32_t ah[2][4], al[2][4];
            #pragma unroll
            for (int mt = 0; mt < 2; mt++) {
                int o0 = (wr * 32 + mt * 16 + rowt) * PJ_S + co + colt;
                int o1 = o0 + 8 * PJ_S;
                ah[mt][0] = su[PJ_AH + o0];      ah[mt][1] = su[PJ_AH + o1];
                ah[mt][2] = su[PJ_AH + o0 + 4];  ah[mt][3] = su[PJ_AH + o1 + 4];
                al[mt][0] = su[PJ_AL + o0];      al[mt][1] = su[PJ_AL + o1];
                al[mt][2] = su[PJ_AL + o0 + 4];  al[mt][3] = su[PJ_AL + o1 + 4];
            }
            #pragma unroll
            for (int nt = 0; nt < 4; nt++) {
                int ob = (wc * 32 + nt * 8 + rowt) * PJ_S + co + colt;
                uint32_t bh0 = su[PJ_BH + ob], bh1 = su[PJ_BH + ob + 4];
                uint32_t bl0 = su[PJ_BL + ob], bl1 = su[PJ_BL + ob + 4];
                #pragma unroll
                for (int mt = 0; mt < 2; mt++) {
                    mma_f16(acc[mt][nt], ah[mt][0], ah[mt][1], ah[mt][2], ah[mt][3], bh0, bh1);
                    mma_f16(acc[mt][nt], ah[mt][0], ah[mt][1], ah[mt][2], ah[mt][3], bl0, bl1);
                    mma_f16(acc[mt][nt], al[mt][0], al[mt][1], al[mt][2], al[mt][3], bh0, bh1);
                }
            }
        }
        __syncthreads();
    }

    #pragma unroll
    for (int mt = 0; mt < 2; mt++) {
        int gr = row0 + wr * 32 + mt * 16 + rowt;
        #pragma unroll
        for (int nt = 0; nt < 4; nt++) {
            int gc = wc * 32 + nt * 8 + colt * 2;
            float2 c01 = { acc[mt][nt][0], acc[mt][nt][1] };
            float2 c23 = { acc[mt][nt][2], acc[mt][nt][3] };
            *(float2*)(Y + (size_t)gr * DK + gc)       = c01;
            *(float2*)(Y + (size_t)(gr + 8) * DK + gc) = c23;
        }
    }
}

// ===================== fp16 tensor-core flash attention, 512 thr ==================
// BQ=BK=128, 16 warps (4x4), warp tile 32x32.
// P stored hi-only (fp16): PV = Ph*Vh + Ph*Vl (residual of P dropped; ~1e-4 rel).

#define AQ_S  68
#define AV_S  136
#define U_Q   0            // Qh @0, Ql @8704          (17408 u32)
#define U_KV  17408        // Kh/Vh @+0, Kl/Vl @+8704  (17408 u32)
#define U_P   34816        // Ph only                   (8704 u32)
#define U_RM  43520        // redmax: 128 rows x 4 partials
#define U_RS  44032        // redsum: 128 rows x 4 partials
#define A_SMEM_BYTES ((44544) * 4)    // 178,176 B

__global__ __launch_bounds__(512) void attn_tc(const int* __restrict__ mask,
                                               float* __restrict__ out)
{
    extern __shared__ uint32_t su[];
    float* redm = (float*)&su[U_RM];
    float* reds = (float*)&su[U_RS];

    const int tid = threadIdx.x;
    const int wid = tid >> 5, lane = tid & 31;
    const int wr = wid >> 2, wc = wid & 3;
    const int rowt = lane >> 2, colt = lane & 3;
    const int qt = blockIdx.x, b = blockIdx.y;

    const float4* Qg = (const float4*)(g_q + ((size_t)b * S_ + (size_t)qt * 128) * DK);
    const float4* Kg = (const float4*)(g_k + (size_t)b * S_ * DK);
    const float4* Vg = (const float4*)(g_v + (size_t)b * S_ * DK);

    // ---- stage Q packed hi/lo ----
    #pragma unroll
    for (int t = 0; t < 8; t++) {
        int idx = tid + t * 512;
        int row = idx >> 5, f4 = idx & 31;
        float4 q = Qg[idx];
        uint32_t h0, l0, h1, l1;
        split2h(q.x, q.y, h0, l0);
        split2h(q.z, q.w, h1, l1);
        *(uint2*)&su[U_Q + row * AQ_S + f4 * 2]        = make_uint2(h0, h1);
        *(uint2*)&su[U_Q + 8704 + row * AQ_S + f4 * 2] = make_uint2(l0, l1);
    }

    float acc[2][4][4];
    #pragma unroll
    for (int mt = 0; mt < 2; mt++)
        #pragma unroll
        for (int nt = 0; nt < 4; nt++)
            #pragma unroll
            for (int i = 0; i < 4; i++) acc[mt][nt][i] = 0.f;

    float mrow[4] = {-1e30f, -1e30f, -1e30f, -1e30f};
    float lrow[4] = {0.f, 0.f, 0.f, 0.f};
    const float scale = 0.08838834764831845f;

    #pragma unroll 1
    for (int kt = 0; kt < S_ / 128; kt++) {
        __syncthreads();
        // ---- stage K packed hi/lo ----
        const float4* Ksrc = Kg + (size_t)kt * 128 * 32;
        #pragma unroll
        for (int t = 0; t < 8; t++) {
            int idx = tid + t * 512;
            int row = idx >> 5, f4 = idx & 31;
            float4 k = Ksrc[idx];
            uint32_t h0, l0, h1, l1;
            split2h(k.x, k.y, h0, l0);
            split2h(k.z, k.w, h1, l1);
            *(uint2*)&su[U_KV + row * AQ_S + f4 * 2]        = make_uint2(h0, h1);
            *(uint2*)&su[U_KV + 8704 + row * AQ_S + f4 * 2] = make_uint2(l0, l1);
        }
        __syncthreads();

        // ---- S = Q K^T (3-term fp16 split) ----
        float s[2][4][4];
        #pragma unroll
        for (int mt = 0; mt < 2; mt++)
            #pragma unroll
            for (int nt = 0; nt < 4; nt++)
                #pragma unroll
                for (int i = 0; i < 4; i++) s[mt][nt][i] = 0.f;

        #pragma unroll 1
        for (int c = 0; c < 8; c++) {
            const int co = c * 8;
            uint32_t ah[2][4], al[2][4];
            #pragma unroll
            for (int mt = 0; mt < 2; mt++) {
                int o0 = (wr * 32 + mt * 16 + rowt) * AQ_S + co + colt;
                int o1 = o0 + 8 * AQ_S;
                ah[mt][0] = su[U_Q + o0];      ah[mt][1] = su[U_Q + o1];
                ah[mt][2] = su[U_Q + o0 + 4];  ah[mt][3] = su[U_Q + o1 + 4];
                al[mt][0] = su[U_Q + 8704 + o0];      al[mt][1] = su[U_Q + 8704 + o1];
                al[mt][2] = su[U_Q + 8704 + o0 + 4];  al[mt][3] = su[U_Q + 8704 + o1 + 4];
            }
            #pragma unroll
            for (int nt = 0; nt < 4; nt++) {
                int ob = (wc * 32 + nt * 8 + rowt) * AQ_S + co + colt;
                uint32_t bh0 = su[U_KV + ob], bh1 = su[U_KV + ob + 4];
                uint32_t bl0 = su[U_KV + 8704 + ob], bl1 = su[U_KV + 8704 + ob + 4];
                #pragma unroll
                for (int mt = 0; mt < 2; mt++) {
                    mma_f16(s[mt][nt], ah[mt][0], ah[mt][1], ah[mt][2], ah[mt][3], bh0, bh1);
                    mma_f16(s[mt][nt], ah[mt][0], ah[mt][1], ah[mt][2], ah[mt][3], bl0, bl1);
                    mma_f16(s[mt][nt], al[mt][0], al[mt][1], al[mt][2], al[mt][3], bh0, bh1);
                }
            }
        }

        // ---- mask + scale; per-warp partial row max ----
        const int* mbase = mask + ((size_t)b * S_ + (size_t)qt * 128) * S_ + (size_t)kt * 128
                                + wc * 32 + colt * 2;
        #pragma unroll
        for (int mt = 0; mt < 2; mt++) {
            int r0 = wr * 32 + mt * 16 + rowt;
            const int* m0p = mbase + (size_t)r0 * S_;
            const int* m1p = mbase + (size_t)(r0 + 8) * S_;
            float mx0 = -1e30f, mx1 = -1e30f;
            #pragma unroll
            for (int nt = 0; nt < 4; nt++) {
                int2 ma = *(const int2*)(m0p + nt * 8);
                int2 mb = *(const int2*)(m1p + nt * 8);
                s[mt][nt][0] = ma.x ? s[mt][nt][0] * scale : -1e9f;
                s[mt][nt][1] = ma.y ? s[mt][nt][1] * scale : -1e9f;
                s[mt][nt][2] = mb.x ? s[mt][nt][2] * scale : -1e9f;
                s[mt][nt][3] = mb.y ? s[mt][nt][3] * scale : -1e9f;
                mx0 = fmaxf(mx0, fmaxf(s[mt][nt][0], s[mt][nt][1]));
                mx1 = fmaxf(mx1, fmaxf(s[mt][nt][2], s[mt][nt][3]));
            }
            mx0 = fmaxf(mx0, __shfl_xor_sync(0xffffffffu, mx0, 1));
            mx0 = fmaxf(mx0, __shfl_xor_sync(0xffffffffu, mx0, 2));
            mx1 = fmaxf(mx1, __shfl_xor_sync(0xffffffffu, mx1, 1));
            mx1 = fmaxf(mx1, __shfl_xor_sync(0xffffffffu, mx1, 2));
            if (colt == 0) {
                redm[r0 * 4 + wc]       = mx0;
                redm[(r0 + 8) * 4 + wc] = mx1;
            }
        }
        __syncthreads();

        // ---- stage V packed-along-k hi/lo (over K buffer) ----
        const float4* Vsrc = Vg + (size_t)kt * 128 * 32;
        #pragma unroll
        for (int t = 0; t < 4; t++) {
            int idx = tid + t * 512;
            int kp = idx >> 5, n4 = idx & 31;
            float4 va = Vsrc[(size_t)(2 * kp) * 32 + n4];
            float4 vb = Vsrc[(size_t)(2 * kp + 1) * 32 + n4];
            uint32_t h[4], l[4];
            split2h(va.x, vb.x, h[0], l[0]);
            split2h(va.y, vb.y, h[1], l[1]);
            split2h(va.z, vb.z, h[2], l[2]);
            split2h(va.w, vb.w, h[3], l[3]);
            *(uint4*)&su[U_KV + kp * AV_S + n4 * 4]        = make_uint4(h[0], h[1], h[2], h[3]);
            *(uint4*)&su[U_KV + 8704 + kp * AV_S + n4 * 4] = make_uint4(l[0], l[1], l[2], l[3]);
        }

        // ---- softmax: exp, partial sums, rescale acc, write Ph (hi only) ----
        float crr[4];
        #pragma unroll
        for (int mt = 0; mt < 2; mt++) {
            int r0 = wr * 32 + mt * 16 + rowt;
            int r1 = r0 + 8;
            float mn0 = fmaxf(fmaxf(redm[r0 * 4], redm[r0 * 4 + 1]),
                              fmaxf(redm[r0 * 4 + 2], redm[r0 * 4 + 3]));
            float mn1 = fmaxf(fmaxf(redm[r1 * 4], redm[r1 * 4 + 1]),
                              fmaxf(redm[r1 * 4 + 2], redm[r1 * 4 + 3]));
            mn0 = fmaxf(mrow[mt*2], mn0);
            mn1 = fmaxf(mrow[mt*2+1], mn1);
            crr[mt*2]   = __expf(mrow[mt*2]   - mn0);
            crr[mt*2+1] = __expf(mrow[mt*2+1] - mn1);
            mrow[mt*2] = mn0;  mrow[mt*2+1] = mn1;
            float sm0 = 0.f, sm1 = 0.f;
            #pragma unroll
            for (int nt = 0; nt < 4; nt++) {
                float p0 = __expf(s[mt][nt][0] - mn0);
                float p1 = __expf(s[mt][nt][1] - mn0);
                float p2 = __expf(s[mt][nt][2] - mn1);
                float p3 = __expf(s[mt][nt][3] - mn1);
                sm0 += p0 + p1;  sm1 += p2 + p3;
                int pc = wc * 16 + nt * 4 + colt;
                su[U_P + r0 * AQ_S + pc] = pack2h(p0, p1);
                su[U_P + r1 * AQ_S + pc] = pack2h(p2, p3);
                acc[mt][nt][0] *= crr[mt*2];   acc[mt][nt][1] *= crr[mt*2];
                acc[mt][nt][2] *= crr[mt*2+1]; acc[mt][nt][3] *= crr[mt*2+1];
            }
            sm0 += __shfl_xor_sync(0xffffffffu, sm0, 1);
            sm0 += __shfl_xor_sync(0xffffffffu, sm0, 2);
            sm1 += __shfl_xor_sync(0xffffffffu, sm1, 1);
            sm1 += __shfl_xor_sync(0xffffffffu, sm1, 2);
            if (colt == 0) {
                reds[r0 * 4 + wc] = sm0;
                reds[r1 * 4 + wc] = sm1;
            }
        }
        __syncthreads();

        // ---- update l ----
        #pragma unroll
        for (int mt = 0; mt < 2; mt++) {
            int r0 = wr * 32 + mt * 16 + rowt;
            int r1 = r0 + 8;
            lrow[mt*2]   = lrow[mt*2]   * crr[mt*2]
                         + reds[r0*4] + reds[r0*4+1] + reds[r0*4+2] + reds[r0*4+3];
            lrow[mt*2+1] = lrow[mt*2+1] * crr[mt*2+1]
                         + reds[r1*4] + reds[r1*4+1] + reds[r1*4+2] + reds[r1*4+3];
        }

        // ---- acc += Ph * (Vh + Vl)  (2 mmas per tile) ----
        #pragma unroll 1
        for (int c = 0; c < 8; c++) {
            const int co = c * 8;
            uint32_t ah[2][4];
            #pragma unroll
            for (int mt = 0; mt < 2; mt++) {
                int o0 = (wr * 32 + mt * 16 + rowt) * AQ_S + co + colt;
                int o1 = o0 + 8 * AQ_S;
                ah[mt][0] = su[U_P + o0];      ah[mt][1] = su[U_P + o1];
                ah[mt][2] = su[U_P + o0 + 4];  ah[mt][3] = su[U_P + o1 + 4];
            }
            #pragma unroll
            for (int nt = 0; nt < 4; nt++) {
                int ob = (co + colt) * AV_S + wc * 32 + nt * 8 + rowt;
                uint32_t bh0 = su[U_KV + ob], bh1 = su[U_KV + ob + 4 * AV_S];
                uint32_t bl0 = su[U_KV + 8704 + ob], bl1 = su[U_KV + 8704 + ob + 4 * AV_S];
                #pragma unroll
                for (int mt = 0; mt < 2; mt++) {
                    mma_f16(acc[mt][nt], ah[mt][0], ah[mt][1], ah[mt][2], ah[mt][3], bh0, bh1);
                    mma_f16(acc[mt][nt], ah[mt][0], ah[mt][1], ah[mt][2], ah[mt][3], bl0, bl1);
                }
            }
        }
    }

    // ---- epilogue ----
    #pragma unroll
    for (int mt = 0; mt < 2; mt++) {
        int r0 = wr * 32 + mt * 16 + rowt;
        float il0 = 1.f / lrow[mt*2];
        float il1 = 1.f / lrow[mt*2+1];
        size_t gr = (size_t)b * S_ + (size_t)qt * 128 + r0;
        #pragma unroll
        for (int nt = 0; nt < 4; nt++) {
            int c0 = wc * 32 + nt * 8 + colt * 2;
            float2 o0 = { acc[mt][nt][0] * il0, acc[mt][nt][1] * il0 };
            float2 o1 = { acc[mt][nt][2] * il1, acc[mt][nt][3] * il1 };
            *(float2*)(out + gr * DK + c0)       = o0;
            *(float2*)(out + (gr + 8) * DK + c0) = o1;
        }
    }
}

// ===================== launch =====================
extern "C" void kernel_launch(void* const* d_in, const int* in_sizes, int n_in,
                              void* d_out, int out_size)
{
    const float* query = (const float*)d_in[0];
    const float* key   = (const float*)d_in[1];
    const float* value = (const float*)d_in[2];
    const int*   maskp = (const int*)  d_in[3];
    const float* Wq    = (const float*)d_in[4];
    const float* Wk    = (const float*)d_in[5];
    const float* Wv    = (const float*)d_in[6];
    float* out = (float*)d_out;

    cudaFuncSetAttribute(proj_mma, cudaFuncAttributeMaxDynamicSharedMemorySize,
                         (int)PJ_SMEM_BYTES);
    cudaFuncSetAttribute(attn_tc, cudaFuncAttributeMaxDynamicSharedMemorySize,
                         (int)A_SMEM_BYTES);

    proj_mma<<<dim3(NROWS / 128, 3), 512, PJ_SMEM_BYTES>>>(query, key, value, Wq, Wk, Wv);
    attn_tc<<<dim3(S_ / 128, B_), 512, A_SMEM_BYTES>>>(maskp, out);
}